// round 7
// baseline (speedup 1.0000x reference)
#include <cuda_runtime.h>
#include <cuda_fp16.h>
#include <cstdint>

#define DEVINL static __device__ __forceinline__

// ===================== compile-time int-list machinery =====================
template<int... Is> struct IL { static constexpr int size = sizeof...(Is); };

template<int H, typename L> struct Prepend;
template<int H, int... Is> struct Prepend<H, IL<Is...>> { using type = IL<H, Is...>; };

template<typename A, typename B> struct Concat;
template<int... As, int... Bs> struct Concat<IL<As...>, IL<Bs...>> { using type = IL<As..., Bs...>; };

template<int I, typename L> struct Get;
template<int H, int... T> struct Get<0, IL<H, T...>> { static constexpr int value = H; };
template<int I, int H, int... T> struct Get<I, IL<H, T...>> { static constexpr int value = Get<I-1, IL<T...>>::value; };

template<int N, typename L> struct Take;
template<> struct Take<0, IL<>> { using type = IL<>; };
template<int H, int... T> struct Take<0, IL<H, T...>> { using type = IL<>; };
template<int N, int H, int... T> struct Take<N, IL<H, T...>> {
  using type = typename Prepend<H, typename Take<N-1, IL<T...>>::type>::type;
};

template<int N, typename L> struct Drop;
template<> struct Drop<0, IL<>> { using type = IL<>; };
template<int H, int... T> struct Drop<0, IL<H, T...>> { using type = IL<H, T...>; };
template<int N, int H, int... T> struct Drop<N, IL<H, T...>> { using type = typename Drop<N-1, IL<T...>>::type; };

template<typename L> struct EvenOdd;
template<> struct EvenOdd<IL<>> { using even = IL<>; using odd = IL<>; };
template<int A> struct EvenOdd<IL<A>> { using even = IL<A>; using odd = IL<>; };
template<int A, int Bv, int... R> struct EvenOdd<IL<A, Bv, R...>> {
  using even = typename Prepend<A,  typename EvenOdd<IL<R...>>::even>::type;
  using odd  = typename Prepend<Bv, typename EvenOdd<IL<R...>>::odd >::type;
};

template<typename E, typename O> struct Interleave;
template<typename E> struct Interleave<E, IL<>> { using type = E; };
template<int E0, int... Es, int O0, int... Os>
struct Interleave<IL<E0, Es...>, IL<O0, Os...>> {
  using type = typename Concat<IL<E0, O0>, typename Interleave<IL<Es...>, IL<Os...>>::type>::type;
};

// ===================== packed f16x2 compare-exchange =====================
DEVINL void cas_(__half2& x, __half2& y) {
  __half2 lo = __hmin2(x, y);
  __half2 hi = __hmax2(x, y);
  x = lo; y = hi;
}

// cleanup step of odd-even merge: cas(O[i], E[i+1])
template<typename E, typename O> struct Cleanup {
  DEVINL void run(__half2*) {}
};
template<int E0, int E1, int... Es, int O0, int... Os>
struct Cleanup<IL<E0, E1, Es...>, IL<O0, Os...>> {
  DEVINL void run(__half2* v) {
    cas_(v[O0], v[E1]);
    Cleanup<IL<E1, Es...>, IL<Os...>>::run(v);
  }
};

// ===================== generalized Batcher odd-even merge =====================
template<typename A, typename B, int M = A::size, int N = B::size>
struct Merge {
  using ME = Merge<typename EvenOdd<A>::even, typename EvenOdd<B>::even>;
  using MO = Merge<typename EvenOdd<A>::odd,  typename EvenOdd<B>::odd >;
  using E = typename ME::type;
  using O = typename MO::type;
  using type = typename Interleave<E, O>::type;
  DEVINL void run(__half2* v) { ME::run(v); MO::run(v); Cleanup<E, O>::run(v); }
};
template<typename A, typename B, int N> struct Merge<A, B, 0, N> { using type = B; DEVINL void run(__half2*) {} };
template<typename A, typename B, int M> struct Merge<A, B, M, 0> { using type = A; DEVINL void run(__half2*) {} };
template<typename A, typename B>        struct Merge<A, B, 0, 0> { using type = IL<>; DEVINL void run(__half2*) {} };
template<typename A, typename B> struct Merge<A, B, 1, 1> {
  static constexpr int a0 = Get<0, A>::value;
  static constexpr int b0 = Get<0, B>::value;
  using type = IL<a0, b0>;
  DEVINL void run(__half2* v) { cas_(v[a0], v[b0]); }
};

// odd-even merge sort
template<typename L, int N = L::size>
struct Sort {
  static constexpr int Half = N / 2;
  using SA = Sort<typename Take<Half, L>::type>;
  using SB = Sort<typename Drop<Half, L>::type>;
  using MG = Merge<typename SA::type, typename SB::type>;
  using type = typename MG::type;
  DEVINL void run(__half2* v) { SA::run(v); SB::run(v); MG::run(v); }
};
template<typename L> struct Sort<L, 0> { using type = IL<>; DEVINL void run(__half2*) {} };
template<typename L> struct Sort<L, 1> { using type = L;    DEVINL void run(__half2*) {} };

template<int S, int N> struct Range {
  using type = typename Prepend<S, typename Range<S+1, N-1>::type>::type;
};
template<int S> struct Range<S, 0> { using type = IL<>; };

// ===================== opaque smem ld/st + bit casts =====================
DEVINL uint32_t s2u(const void* p) { return (uint32_t)__cvta_generic_to_shared(p); }
DEVINL void sts_u(uint32_t a, uint32_t v) {
  asm volatile("st.shared.b32 [%0], %1;" :: "r"(a), "r"(v) : "memory");
}
DEVINL uint32_t lds_u(uint32_t a) {
  uint32_t v;
  asm volatile("ld.shared.b32 %0, [%1];" : "=r"(v) : "r"(a) : "memory");
  return v;
}
DEVINL uint32_t h2u(__half2 h) { return *reinterpret_cast<uint32_t*>(&h); }
DEVINL __half2 u2h(uint32_t u) { return *reinterpret_cast<__half2*>(&u); }

// ===================== problem constants =====================
constexpr int Bn = 4, Hn = 256, Wn = 256, Cn = 16;
constexpr int TX = 8, TY = 8;              // output pixels per block: 64
constexpr int TW = TX + 6, TH = TY + 6;    // 14 x 14 haloed tile
constexpr int NPIX = TX * TY;              // 64
constexpr int NPR  = Cn / 2;               // 8 channel-pairs
constexpr int NTHREADS = NPIX * NPR;       // 512
constexpr int NA = 23;                     // staged ranks of sorted25: A[2..24]
constexpr int FS = 52;                     // feat / wsmT row stride (16B-aligned)

// dynamic smem layout (bytes)
constexpr int SM_TILE = 0;                              // uint32[TH*TW*NPR] = 6272B
constexpr int SM_WT   = SM_TILE + TH * TW * NPR * 4;    // float[16*FS]     = 3328B
constexpr int SM_FEAT = SM_WT + 16 * FS * 4;            // float[NPIX*FS]   = 13312B
constexpr int SM_AST  = SM_FEAT + NPIX * FS * 4;        // uint32[512*NA]   = 47104B
constexpr int SM_TOTAL = SM_AST + NTHREADS * NA * 4;    // ~70016B

// Slot layout of V: 0..8 inner 3x3, 9..24 ring of 5x5, 25..48 ring of 7x7
using L9  = Range<0, 9>::type;
using L16 = Range<9, 16>::type;
using L24 = Range<25, 24>::type;
using S9  = Sort<L9>;
using S16 = Sort<L16>;
using S24 = Sort<L24>;
using M25 = Merge<typename S9::type, typename S16::type>;
using A25 = typename M25::type;
using B24 = typename S24::type;

// Stage sorted25 ranks R..24 to smem (opaque stores kill register liveness)
template<int R> struct Stage {
  DEVINL void run(const __half2* v, uint32_t ab) {
    sts_u(ab + (R - 2) * 4, h2u(v[Get<R, A25>::value]));
    Stage<R + 1>::run(v, ab);
  }
};
template<> struct Stage<25> { DEVINL void run(const __half2*, uint32_t) {} };

// Selection fold over terms t_i = min(a[i-OFS], B24[26-i]) for i = I, I+2, ...
template<int I, int IEnd, int OFS> struct SelA {
  DEVINL __half2 run(const __half2* v, const __half2* a) {
    __half2 t = __hmin2(a[I - OFS], v[Get<26 - I, B24>::value]);
    return __hmax2(t, SelA<I + 2, IEnd, OFS>::run(v, a));
  }
};
template<int IEnd, int OFS> struct SelA<IEnd, IEnd, OFS> {
  DEVINL __half2 run(const __half2* v, const __half2* a) {
    return __hmin2(a[IEnd - OFS], v[Get<26 - IEnd, B24>::value]);
  }
};

__global__ void __launch_bounds__(NTHREADS, 3)
amblock_kernel(const float* __restrict__ x, const float* __restrict__ w,
               float* __restrict__ out) {
  extern __shared__ __align__(16) char smraw[];
  uint32_t* tile = reinterpret_cast<uint32_t*>(smraw + SM_TILE);  // [TH][TW][NPR]
  float*    wsmT = reinterpret_cast<float*>(smraw + SM_WT);       // [16][FS]
  float*    feat = reinterpret_cast<float*>(smraw + SM_FEAT);     // [NPIX][FS]
  uint32_t* Ast  = reinterpret_cast<uint32_t*>(smraw + SM_AST);   // [NTHREADS][NA]

  const int tid = threadIdx.x;
  const int bx = blockIdx.x, by = blockIdx.y, bz = blockIdx.z;

  // transposed weights: wsmT[o*FS + cc] = w[cc*16 + o]
  for (int i = tid; i < 16 * 48; i += NTHREADS) {
    int o = i & 15, cc = i >> 4;
    wsmT[o * FS + cc] = w[cc * 16 + o];
  }

  // haloed tile -> smem as half2; vectorized: float4 per 4 channels
  const int y0 = by * TY - 3, x0 = bx * TX - 3;
  for (int i = tid; i < TH * TW * 4; i += NTHREADS) {
    int q   = i & 3;       // channel quad: channels 4q..4q+3
    int pos = i >> 2;      // 0..TH*TW-1
    int py = pos / TW, px = pos - py * TW;
    int gy = y0 + py, gx = x0 + px;
    uint2 vv; vv.x = 0u; vv.y = 0u;
    if ((unsigned)gy < (unsigned)Hn && (unsigned)gx < (unsigned)Wn) {
      const float4 f = *reinterpret_cast<const float4*>(
          &x[(((bz * Hn + gy) * Wn) + gx) * Cn + q * 4]);
      vv.x = h2u(__floats2half2_rn(f.x, f.y));
      vv.y = h2u(__floats2half2_rn(f.z, f.w));
    }
    *reinterpret_cast<uint2*>(&tile[pos * NPR + q * 2]) = vv;
  }
  __syncthreads();

  const int c2  = tid & (NPR - 1);   // channel pair
  const int pix = tid >> 3;          // 0..63
  __half2 m7, m3, m5;
  {
    const int pxx = pix & (TX - 1);
    const int pyy = pix >> 3;
    const uint32_t* baseu = &tile[(((pyy + 3) * TW) + (pxx + 3)) * NPR + c2];
    const uint32_t tb = s2u(baseu);
    const uint32_t ab = s2u(&Ast[tid * NA]);

    __half2 V[49];
    // inner 3x3 -> slots 0..8
#pragma unroll
    for (int dy = -1; dy <= 1; dy++)
#pragma unroll
      for (int dx = -1; dx <= 1; dx++)
        V[(dy + 1) * 3 + (dx + 1)] = u2h(baseu[(dy * TW + dx) * NPR]);
    // 5x5 ring -> slots 9..24
    {
      int k = 9;
#pragma unroll
      for (int dy = -2; dy <= 2; dy++)
#pragma unroll
        for (int dx = -2; dx <= 2; dx++)
          if (dy < -1 || dy > 1 || dx < -1 || dx > 1) { V[k] = u2h(baseu[(dy * TW + dx) * NPR]); k++; }
    }

    // k=3: ascending index 6 of sorted 9
    S9::run(V);
    m3 = V[Get<6, typename S9::type>::value];

    // k=5: ascending index 14 of sorted 25
    S16::run(V);
    M25::run(V);
    m5 = V[Get<14, A25>::value];

    // stage sorted25 ranks 2..24 to smem, then load 7x7 ring late
    Stage<2>::run(V, ab);
    {
      int k = 25;
#pragma unroll
      for (int dy = -3; dy <= 3; dy++)
#pragma unroll
        for (int dx = -3; dx <= 3; dx++)
          if (dy < -2 || dy > 2 || dx < -2 || dx > 2) { V[k] = u2h(lds_u(tb + (dy * TW + dx) * (NPR * 4))); k++; }
    }

    S24::run(V);

    // k=7: rank 26 of union: m7 = max(A[2], B[1], max_{i=3..24} min(A[i], B[26-i]))
    {
      __half2 a[11];
#pragma unroll
      for (int r = 0; r < 11; r++) a[r] = u2h(lds_u(ab + (1 + r) * 4));  // A[3..13]
      __half2 acc = __hmax2(u2h(lds_u(ab + 0)), V[Get<1, B24>::value]);  // A[2], B[1]
      acc = __hmax2(acc, SelA<3, 13, 3>::run(V, a));
      acc = __hmax2(acc, SelA<4, 12, 3>::run(V, a));
#pragma unroll
      for (int r = 0; r < 11; r++) a[r] = u2h(lds_u(ab + (12 + r) * 4)); // A[14..24]
      acc = __hmax2(acc, SelA<14, 24, 14>::run(V, a));
      acc = __hmax2(acc, SelA<15, 23, 14>::run(V, a));
      m7 = acc;
    }
  }

  // feat is a separate buffer (no overlay) -> no barrier needed before writes
  {
    float* fp = &feat[pix * FS];
    float2 f7 = __half22float2(m7);
    float2 f3 = __half22float2(m3);
    float2 f5 = __half22float2(m5);
    *reinterpret_cast<float2*>(&fp[     2 * c2]) = f7;
    *reinterpret_cast<float2*>(&fp[16 + 2 * c2]) = f3;
    *reinterpret_cast<float2*>(&fp[32 + 2 * c2]) = f5;
  }
  __syncthreads();

  // fused 1x1 conv (fp32): thread computes output channel o for 2 pixels
  {
    const int o  = tid & 15;
    const int p0 = tid >> 4;                 // pixels p0 and p0+32
    const float4* wrow = reinterpret_cast<const float4*>(&wsmT[o * FS]);
    const float4* f0   = reinterpret_cast<const float4*>(&feat[p0 * FS]);
    const float4* f1   = reinterpret_cast<const float4*>(&feat[(p0 + 32) * FS]);
    float acc0 = 0.f, acc1 = 0.f;
#pragma unroll
    for (int q = 0; q < 12; q++) {
      const float4 wv = wrow[q];
      const float4 av = f0[q];
      const float4 bv = f1[q];
      acc0 = fmaf(av.x, wv.x, acc0); acc1 = fmaf(bv.x, wv.x, acc1);
      acc0 = fmaf(av.y, wv.y, acc0); acc1 = fmaf(bv.y, wv.y, acc1);
      acc0 = fmaf(av.z, wv.z, acc0); acc1 = fmaf(bv.z, wv.z, acc1);
      acc0 = fmaf(av.w, wv.w, acc0); acc1 = fmaf(bv.w, wv.w, acc1);
    }
    const int px0 = p0 & (TX - 1), py0 = p0 >> 3;       // pixel p0
    const int py1 = py0 + 4;                            // pixel p0+32 (same px)
    out[(((bz * Hn + by * TY + py0) * Wn) + bx * TX + px0) * Cn + o] = acc0;
    out[(((bz * Hn + by * TY + py1) * Wn) + bx * TX + px0) * Cn + o] = acc1;
  }
}

extern "C" void kernel_launch(void* const* d_in, const int* in_sizes, int n_in,
                              void* d_out, int out_size) {
  const float* x = (const float*)d_in[0];
  const float* w = (const float*)d_in[1];
  float* out = (float*)d_out;
  cudaFuncSetAttribute(amblock_kernel,
                       cudaFuncAttributeMaxDynamicSharedMemorySize, SM_TOTAL);
  dim3 grid(Wn / TX, Hn / TY, Bn);
  amblock_kernel<<<grid, NTHREADS, SM_TOTAL>>>(x, w, out);
}

// round 8
// speedup vs baseline: 1.0941x; 1.0941x over previous
#include <cuda_runtime.h>
#include <cuda_fp16.h>
#include <cstdint>

#define DEVINL static __device__ __forceinline__

// ===================== compile-time int-list machinery =====================
template<int... Is> struct IL { static constexpr int size = sizeof...(Is); };

template<int H, typename L> struct Prepend;
template<int H, int... Is> struct Prepend<H, IL<Is...>> { using type = IL<H, Is...>; };

template<typename A, typename B> struct Concat;
template<int... As, int... Bs> struct Concat<IL<As...>, IL<Bs...>> { using type = IL<As..., Bs...>; };

template<int I, typename L> struct Get;
template<int H, int... T> struct Get<0, IL<H, T...>> { static constexpr int value = H; };
template<int I, int H, int... T> struct Get<I, IL<H, T...>> { static constexpr int value = Get<I-1, IL<T...>>::value; };

template<int N, typename L> struct Take;
template<> struct Take<0, IL<>> { using type = IL<>; };
template<int H, int... T> struct Take<0, IL<H, T...>> { using type = IL<>; };
template<int N, int H, int... T> struct Take<N, IL<H, T...>> {
  using type = typename Prepend<H, typename Take<N-1, IL<T...>>::type>::type;
};

template<int N, typename L> struct Drop;
template<> struct Drop<0, IL<>> { using type = IL<>; };
template<int H, int... T> struct Drop<0, IL<H, T...>> { using type = IL<H, T...>; };
template<int N, int H, int... T> struct Drop<N, IL<H, T...>> { using type = typename Drop<N-1, IL<T...>>::type; };

template<typename L> struct EvenOdd;
template<> struct EvenOdd<IL<>> { using even = IL<>; using odd = IL<>; };
template<int A> struct EvenOdd<IL<A>> { using even = IL<A>; using odd = IL<>; };
template<int A, int Bv, int... R> struct EvenOdd<IL<A, Bv, R...>> {
  using even = typename Prepend<A,  typename EvenOdd<IL<R...>>::even>::type;
  using odd  = typename Prepend<Bv, typename EvenOdd<IL<R...>>::odd >::type;
};

template<typename E, typename O> struct Interleave;
template<typename E> struct Interleave<E, IL<>> { using type = E; };
template<int E0, int... Es, int O0, int... Os>
struct Interleave<IL<E0, Es...>, IL<O0, Os...>> {
  using type = typename Concat<IL<E0, O0>, typename Interleave<IL<Es...>, IL<Os...>>::type>::type;
};

// ===================== packed f16x2 compare-exchange =====================
DEVINL void cas_(__half2& x, __half2& y) {
  __half2 lo = __hmin2(x, y);
  __half2 hi = __hmax2(x, y);
  x = lo; y = hi;
}

// cleanup step of odd-even merge: cas(O[i], E[i+1])
template<typename E, typename O> struct Cleanup {
  DEVINL void run(__half2*) {}
};
template<int E0, int E1, int... Es, int O0, int... Os>
struct Cleanup<IL<E0, E1, Es...>, IL<O0, Os...>> {
  DEVINL void run(__half2* v) {
    cas_(v[O0], v[E1]);
    Cleanup<IL<E1, Es...>, IL<Os...>>::run(v);
  }
};

// ===================== generalized Batcher odd-even merge =====================
template<typename A, typename B, int M = A::size, int N = B::size>
struct Merge {
  using ME = Merge<typename EvenOdd<A>::even, typename EvenOdd<B>::even>;
  using MO = Merge<typename EvenOdd<A>::odd,  typename EvenOdd<B>::odd >;
  using E = typename ME::type;
  using O = typename MO::type;
  using type = typename Interleave<E, O>::type;
  DEVINL void run(__half2* v) { ME::run(v); MO::run(v); Cleanup<E, O>::run(v); }
};
template<typename A, typename B, int N> struct Merge<A, B, 0, N> { using type = B; DEVINL void run(__half2*) {} };
template<typename A, typename B, int M> struct Merge<A, B, M, 0> { using type = A; DEVINL void run(__half2*) {} };
template<typename A, typename B>        struct Merge<A, B, 0, 0> { using type = IL<>; DEVINL void run(__half2*) {} };
template<typename A, typename B> struct Merge<A, B, 1, 1> {
  static constexpr int a0 = Get<0, A>::value;
  static constexpr int b0 = Get<0, B>::value;
  using type = IL<a0, b0>;
  DEVINL void run(__half2* v) { cas_(v[a0], v[b0]); }
};

// odd-even merge sort
template<typename L, int N = L::size>
struct Sort {
  static constexpr int Half = N / 2;
  using SA = Sort<typename Take<Half, L>::type>;
  using SB = Sort<typename Drop<Half, L>::type>;
  using MG = Merge<typename SA::type, typename SB::type>;
  using type = typename MG::type;
  DEVINL void run(__half2* v) { SA::run(v); SB::run(v); MG::run(v); }
};
template<typename L> struct Sort<L, 0> { using type = IL<>; DEVINL void run(__half2*) {} };
template<typename L> struct Sort<L, 1> { using type = L;    DEVINL void run(__half2*) {} };

template<int S, int N> struct Range {
  using type = typename Prepend<S, typename Range<S+1, N-1>::type>::type;
};
template<int S> struct Range<S, 0> { using type = IL<>; };

// ===================== opaque smem ld/st + bit casts =====================
DEVINL uint32_t s2u(const void* p) { return (uint32_t)__cvta_generic_to_shared(p); }
DEVINL void sts_u(uint32_t a, uint32_t v) {
  asm volatile("st.shared.b32 [%0], %1;" :: "r"(a), "r"(v) : "memory");
}
DEVINL uint32_t lds_u(uint32_t a) {
  uint32_t v;
  asm volatile("ld.shared.b32 %0, [%1];" : "=r"(v) : "r"(a) : "memory");
  return v;
}
DEVINL uint32_t h2u(__half2 h) { return *reinterpret_cast<uint32_t*>(&h); }
DEVINL __half2 u2h(uint32_t u) { return *reinterpret_cast<__half2*>(&u); }

// ===================== problem constants =====================
constexpr int Bn = 4, Hn = 256, Wn = 256, Cn = 16;
constexpr int TX = 8, TY = 4;              // output pixels per block: 32
constexpr int TW = TX + 6, TH = TY + 6;    // 14 x 10 haloed tile
constexpr int NPIX = TX * TY;              // 32
constexpr int NPR  = Cn / 2;               // 8 channel-pairs
constexpr int NTHREADS = NPIX * NPR;       // 256
constexpr int NA = 23;                     // staged ranks of sorted25: A[2..24]
constexpr int FS = 52;                     // feat / wsmT row stride (16B-aligned)

// Slot layout of V: 0..8 inner 3x3, 9..24 ring of 5x5, 25..48 ring of 7x7
using L9  = Range<0, 9>::type;
using L16 = Range<9, 16>::type;
using L24 = Range<25, 24>::type;
using S9  = Sort<L9>;
using S16 = Sort<L16>;
using S24 = Sort<L24>;
using M25 = Merge<typename S9::type, typename S16::type>;
using A25 = typename M25::type;
using B24 = typename S24::type;

// Stage sorted25 ranks R..24 to smem (opaque stores kill register liveness)
template<int R> struct Stage {
  DEVINL void run(const __half2* v, uint32_t ab) {
    sts_u(ab + (R - 2) * 4, h2u(v[Get<R, A25>::value]));
    Stage<R + 1>::run(v, ab);
  }
};
template<> struct Stage<25> { DEVINL void run(const __half2*, uint32_t) {} };

// Selection fold over terms t_i = min(a[i-OFS], B24[26-i]) for i = I, I+2, ...
template<int I, int IEnd, int OFS> struct SelA {
  DEVINL __half2 run(const __half2* v, const __half2* a) {
    __half2 t = __hmin2(a[I - OFS], v[Get<26 - I, B24>::value]);
    return __hmax2(t, SelA<I + 2, IEnd, OFS>::run(v, a));
  }
};
template<int IEnd, int OFS> struct SelA<IEnd, IEnd, OFS> {
  DEVINL __half2 run(const __half2* v, const __half2* a) {
    return __hmin2(a[IEnd - OFS], v[Get<26 - IEnd, B24>::value]);
  }
};

__global__ void __launch_bounds__(NTHREADS, 7)
amblock_kernel(const float* __restrict__ x, const float* __restrict__ w,
               float* __restrict__ out) {
  // Overlay A: tile (4480B) / feat (6656B) share upool (disjoint lifetimes)
  // Overlay B: Ast (23552B) / wsmT (3328B) share astpool (Ast dead before conv)
  __shared__ __align__(16) char upool[NPIX * FS * 4];      // 6656B
  __shared__ __align__(16) uint32_t astpool[NTHREADS * NA]; // 23552B

  uint32_t* tile = reinterpret_cast<uint32_t*>(upool);     // [TH][TW][NPR]
  float*    feat = reinterpret_cast<float*>(upool);        // [NPIX][FS]
  uint32_t* Ast  = astpool;                                // [NTHREADS][NA]
  float*    wsmT = reinterpret_cast<float*>(astpool);      // [16][FS] (epilogue)

  const int tid = threadIdx.x;
  const int bx = blockIdx.x, by = blockIdx.y, bz = blockIdx.z;

  // haloed tile -> smem as half2; vectorized: float4 per 4 channels
  const int y0 = by * TY - 3, x0 = bx * TX - 3;
  for (int i = tid; i < TH * TW * 4; i += NTHREADS) {
    int q   = i & 3;       // channel quad: channels 4q..4q+3
    int pos = i >> 2;      // 0..TH*TW-1
    int py = pos / TW, px = pos - py * TW;
    int gy = y0 + py, gx = x0 + px;
    uint2 vv; vv.x = 0u; vv.y = 0u;
    if ((unsigned)gy < (unsigned)Hn && (unsigned)gx < (unsigned)Wn) {
      const float4 f = *reinterpret_cast<const float4*>(
          &x[(((bz * Hn + gy) * Wn) + gx) * Cn + q * 4]);
      vv.x = h2u(__floats2half2_rn(f.x, f.y));
      vv.y = h2u(__floats2half2_rn(f.z, f.w));
    }
    *reinterpret_cast<uint2*>(&tile[pos * NPR + q * 2]) = vv;
  }
  __syncthreads();

  const int c2  = tid & (NPR - 1);   // channel pair
  const int pix = tid >> 3;          // 0..31
  __half2 m7, m3, m5;
  {
    const int pxx = pix & (TX - 1);
    const int pyy = pix >> 3;
    const uint32_t* baseu = &tile[(((pyy + 3) * TW) + (pxx + 3)) * NPR + c2];
    const uint32_t tb = s2u(baseu);
    const uint32_t ab = s2u(&Ast[tid * NA]);

    __half2 V[49];
    // inner 3x3 -> slots 0..8
#pragma unroll
    for (int dy = -1; dy <= 1; dy++)
#pragma unroll
      for (int dx = -1; dx <= 1; dx++)
        V[(dy + 1) * 3 + (dx + 1)] = u2h(baseu[(dy * TW + dx) * NPR]);
    // 5x5 ring -> slots 9..24
    {
      int k = 9;
#pragma unroll
      for (int dy = -2; dy <= 2; dy++)
#pragma unroll
        for (int dx = -2; dx <= 2; dx++)
          if (dy < -1 || dy > 1 || dx < -1 || dx > 1) { V[k] = u2h(baseu[(dy * TW + dx) * NPR]); k++; }
    }

    // k=3: ascending index 6 of sorted 9
    S9::run(V);
    m3 = V[Get<6, typename S9::type>::value];

    // k=5: ascending index 14 of sorted 25
    S16::run(V);
    M25::run(V);
    m5 = V[Get<14, A25>::value];

    // stage sorted25 ranks 2..24 to smem, then load 7x7 ring late
    Stage<2>::run(V, ab);
    {
      int k = 25;
#pragma unroll
      for (int dy = -3; dy <= 3; dy++)
#pragma unroll
        for (int dx = -3; dx <= 3; dx++)
          if (dy < -2 || dy > 2 || dx < -2 || dx > 2) { V[k] = u2h(lds_u(tb + (dy * TW + dx) * (NPR * 4))); k++; }
    }

    S24::run(V);

    // k=7: rank 26 of union: m7 = max(A[2], B[1], max_{i=3..24} min(A[i], B[26-i]))
    // Three reload groups of 8/8/7 (bounded liveness: 24 B + 8 A + accs ~ 36)
    {
      __half2 a[8];
      // group 1: A[2..9]
#pragma unroll
      for (int r = 0; r < 8; r++) a[r] = u2h(lds_u(ab + r * 4));
      __half2 accE = __hmax2(a[0], V[Get<1, B24>::value]);     // A[2], B[1]
      __half2 accO = SelA<3, 9, 2>::run(V, a);                 // i = 3,5,7,9
      accE = __hmax2(accE, SelA<4, 8, 2>::run(V, a));          // i = 4,6,8
      // group 2: A[10..17]
#pragma unroll
      for (int r = 0; r < 8; r++) a[r] = u2h(lds_u(ab + (8 + r) * 4));
      accE = __hmax2(accE, SelA<10, 16, 10>::run(V, a));       // i = 10,12,14,16
      accO = __hmax2(accO, SelA<11, 17, 10>::run(V, a));       // i = 11,13,15,17
      // group 3: A[18..24]
#pragma unroll
      for (int r = 0; r < 7; r++) a[r] = u2h(lds_u(ab + (16 + r) * 4));
      accE = __hmax2(accE, SelA<18, 24, 18>::run(V, a));       // i = 18,20,22,24
      accO = __hmax2(accO, SelA<19, 23, 18>::run(V, a));       // i = 19,21,23
      m7 = __hmax2(accE, accO);
    }
  }

  // tile and Ast are dead; feat overlays tile, wsmT overlays Ast.
  __syncthreads();
  {
    float* fp = &feat[pix * FS];
    float2 f7 = __half22float2(m7);
    float2 f3 = __half22float2(m3);
    float2 f5 = __half22float2(m5);
    *reinterpret_cast<float2*>(&fp[     2 * c2]) = f7;
    *reinterpret_cast<float2*>(&fp[16 + 2 * c2]) = f3;
    *reinterpret_cast<float2*>(&fp[32 + 2 * c2]) = f5;
  }
  // transposed weights into the (dead) staging buffer: wsmT[o*FS+cc] = w[cc*16+o]
  for (int i = tid; i < 16 * 48; i += NTHREADS) {
    int o = i & 15, cc = i >> 4;
    wsmT[o * FS + cc] = w[cc * 16 + o];
  }
  __syncthreads();

  // fused 1x1 conv (fp32): thread computes output channel o for 2 pixels
  {
    const int o  = tid & 15;
    const int p0 = tid >> 4;                 // pixels p0 and p0+16
    const float4* wrow = reinterpret_cast<const float4*>(&wsmT[o * FS]);
    const float4* f0   = reinterpret_cast<const float4*>(&feat[p0 * FS]);
    const float4* f1   = reinterpret_cast<const float4*>(&feat[(p0 + 16) * FS]);
    float acc0 = 0.f, acc1 = 0.f;
#pragma unroll
    for (int q = 0; q < 12; q++) {
      const float4 wv = wrow[q];
      const float4 av = f0[q];
      const float4 bv = f1[q];
      acc0 = fmaf(av.x, wv.x, acc0); acc1 = fmaf(bv.x, wv.x, acc1);
      acc0 = fmaf(av.y, wv.y, acc0); acc1 = fmaf(bv.y, wv.y, acc1);
      acc0 = fmaf(av.z, wv.z, acc0); acc1 = fmaf(bv.z, wv.z, acc1);
      acc0 = fmaf(av.w, wv.w, acc0); acc1 = fmaf(bv.w, wv.w, acc1);
    }
    const int px0 = p0 & (TX - 1), py0 = p0 >> 3;       // pixel p0
    const int px1 = (p0 + 16) & (TX - 1), py1 = (p0 + 16) >> 3;
    out[(((bz * Hn + by * TY + py0) * Wn) + bx * TX + px0) * Cn + o] = acc0;
    out[(((bz * Hn + by * TY + py1) * Wn) + bx * TX + px1) * Cn + o] = acc1;
  }
}

extern "C" void kernel_launch(void* const* d_in, const int* in_sizes, int n_in,
                              void* d_out, int out_size) {
  const float* x = (const float*)d_in[0];
  const float* w = (const float*)d_in[1];
  float* out = (float*)d_out;
  dim3 grid(Wn / TX, Hn / TY, Bn);
  amblock_kernel<<<grid, NTHREADS>>>(x, w, out);
}

// round 10
// speedup vs baseline: 1.1172x; 1.0212x over previous
#include <cuda_runtime.h>
#include <cuda_fp16.h>
#include <cstdint>

#define DEVINL static __device__ __forceinline__

// ===================== compile-time int-list machinery =====================
template<int... Is> struct IL { static constexpr int size = sizeof...(Is); };

template<int H, typename L> struct Prepend;
template<int H, int... Is> struct Prepend<H, IL<Is...>> { using type = IL<H, Is...>; };

template<typename A, typename B> struct Concat;
template<int... As, int... Bs> struct Concat<IL<As...>, IL<Bs...>> { using type = IL<As..., Bs...>; };

template<int I, typename L> struct Get;
template<int H, int... T> struct Get<0, IL<H, T...>> { static constexpr int value = H; };
template<int I, int H, int... T> struct Get<I, IL<H, T...>> { static constexpr int value = Get<I-1, IL<T...>>::value; };

template<int N, typename L> struct Take;
template<> struct Take<0, IL<>> { using type = IL<>; };
template<int H, int... T> struct Take<0, IL<H, T...>> { using type = IL<>; };
template<int N, int H, int... T> struct Take<N, IL<H, T...>> {
  using type = typename Prepend<H, typename Take<N-1, IL<T...>>::type>::type;
};

template<int N, typename L> struct Drop;
template<> struct Drop<0, IL<>> { using type = IL<>; };
template<int H, int... T> struct Drop<0, IL<H, T...>> { using type = IL<H, T...>; };
template<int N, int H, int... T> struct Drop<N, IL<H, T...>> { using type = typename Drop<N-1, IL<T...>>::type; };

template<typename L> struct EvenOdd;
template<> struct EvenOdd<IL<>> { using even = IL<>; using odd = IL<>; };
template<int A> struct EvenOdd<IL<A>> { using even = IL<A>; using odd = IL<>; };
template<int A, int Bv, int... R> struct EvenOdd<IL<A, Bv, R...>> {
  using even = typename Prepend<A,  typename EvenOdd<IL<R...>>::even>::type;
  using odd  = typename Prepend<Bv, typename EvenOdd<IL<R...>>::odd >::type;
};

template<typename E, typename O> struct Interleave;
template<typename E> struct Interleave<E, IL<>> { using type = E; };
template<int E0, int... Es, int O0, int... Os>
struct Interleave<IL<E0, Es...>, IL<O0, Os...>> {
  using type = typename Concat<IL<E0, O0>, typename Interleave<IL<Es...>, IL<Os...>>::type>::type;
};

// ===================== packed f16x2 compare-exchange =====================
DEVINL void cas_(__half2& x, __half2& y) {
  __half2 lo = __hmin2(x, y);
  __half2 hi = __hmax2(x, y);
  x = lo; y = hi;
}

// cleanup step of odd-even merge: cas(O[i], E[i+1])
template<typename E, typename O> struct Cleanup {
  DEVINL void run(__half2*) {}
};
template<int E0, int E1, int... Es, int O0, int... Os>
struct Cleanup<IL<E0, E1, Es...>, IL<O0, Os...>> {
  DEVINL void run(__half2* v) {
    cas_(v[O0], v[E1]);
    Cleanup<IL<E1, Es...>, IL<Os...>>::run(v);
  }
};

// ===================== generalized Batcher odd-even merge =====================
template<typename A, typename B, int M = A::size, int N = B::size>
struct Merge {
  using ME = Merge<typename EvenOdd<A>::even, typename EvenOdd<B>::even>;
  using MO = Merge<typename EvenOdd<A>::odd,  typename EvenOdd<B>::odd >;
  using E = typename ME::type;
  using O = typename MO::type;
  using type = typename Interleave<E, O>::type;
  DEVINL void run(__half2* v) { ME::run(v); MO::run(v); Cleanup<E, O>::run(v); }
};
template<typename A, typename B, int N> struct Merge<A, B, 0, N> { using type = B; DEVINL void run(__half2*) {} };
template<typename A, typename B, int M> struct Merge<A, B, M, 0> { using type = A; DEVINL void run(__half2*) {} };
template<typename A, typename B>        struct Merge<A, B, 0, 0> { using type = IL<>; DEVINL void run(__half2*) {} };
template<typename A, typename B> struct Merge<A, B, 1, 1> {
  static constexpr int a0 = Get<0, A>::value;
  static constexpr int b0 = Get<0, B>::value;
  using type = IL<a0, b0>;
  DEVINL void run(__half2* v) { cas_(v[a0], v[b0]); }
};

// odd-even merge sort
template<typename L, int N = L::size>
struct Sort {
  static constexpr int Half = N / 2;
  using SA = Sort<typename Take<Half, L>::type>;
  using SB = Sort<typename Drop<Half, L>::type>;
  using MG = Merge<typename SA::type, typename SB::type>;
  using type = typename MG::type;
  DEVINL void run(__half2* v) { SA::run(v); SB::run(v); MG::run(v); }
};
template<typename L> struct Sort<L, 0> { using type = IL<>; DEVINL void run(__half2*) {} };
template<typename L> struct Sort<L, 1> { using type = L;    DEVINL void run(__half2*) {} };

template<int S, int N> struct Range {
  using type = typename Prepend<S, typename Range<S+1, N-1>::type>::type;
};
template<int S> struct Range<S, 0> { using type = IL<>; };

// ===================== opaque smem ld/st + bit casts =====================
DEVINL uint32_t s2u(const void* p) { return (uint32_t)__cvta_generic_to_shared(p); }
DEVINL void sts_u(uint32_t a, uint32_t v) {
  asm volatile("st.shared.b32 [%0], %1;" :: "r"(a), "r"(v) : "memory");
}
DEVINL uint32_t lds_u(uint32_t a) {
  uint32_t v;
  asm volatile("ld.shared.b32 %0, [%1];" : "=r"(v) : "r"(a) : "memory");
  return v;
}
DEVINL uint32_t h2u(__half2 h) { return *reinterpret_cast<uint32_t*>(&h); }
DEVINL __half2 u2h(uint32_t u) { return *reinterpret_cast<__half2*>(&u); }

// ===================== problem constants =====================
constexpr int Bn = 4, Hn = 256, Wn = 256, Cn = 16;
constexpr int TX = 8, TY = 4;              // output pixels per block: 32
constexpr int TW = TX + 6, TH = TY + 6;    // 14 x 10 haloed tile
constexpr int NPIX = TX * TY;              // 32
constexpr int NPR  = Cn / 2;               // 8 channel-pairs
constexpr int NTHREADS = NPIX * NPR;       // 256
constexpr int NA = 20;                     // staged ranks of sorted25: A[5..24]
constexpr int FS = 52;                     // feat / wsmT row stride (16B-aligned)

// Slot layout of V: 0..8 inner 3x3, 9..24 ring of 5x5, 25..48 ring of 7x7
using L9  = Range<0, 9>::type;
using L16 = Range<9, 16>::type;
using L24 = Range<25, 24>::type;
using S9  = Sort<L9>;
using S16 = Sort<L16>;
using S24 = Sort<L24>;
using M25 = Merge<typename S9::type, typename S16::type>;
using A25 = typename M25::type;
using B24 = typename S24::type;

// Stage sorted25 ranks R..24 (R starts at 5) to smem
template<int R> struct Stage {
  DEVINL void run(const __half2* v, uint32_t ab) {
    sts_u(ab + (R - 5) * 4, h2u(v[Get<R, A25>::value]));
    Stage<R + 1>::run(v, ab);
  }
};
template<> struct Stage<25> { DEVINL void run(const __half2*, uint32_t) {} };

// Selection fold over terms t_i = min(a[i-OFS], B24[26-i]) for i = I, I+2, ...
template<int I, int IEnd, int OFS> struct SelA {
  DEVINL __half2 run(const __half2* v, const __half2* a) {
    __half2 t = __hmin2(a[I - OFS], v[Get<26 - I, B24>::value]);
    return __hmax2(t, SelA<I + 2, IEnd, OFS>::run(v, a));
  }
};
template<int IEnd, int OFS> struct SelA<IEnd, IEnd, OFS> {
  DEVINL __half2 run(const __half2* v, const __half2* a) {
    return __hmin2(a[IEnd - OFS], v[Get<26 - IEnd, B24>::value]);
  }
};

__global__ void __launch_bounds__(NTHREADS, 8)
amblock_kernel(const float* __restrict__ x, const float* __restrict__ w,
               float* __restrict__ out) {
  // Overlay A: tile (4480B) / feat (6656B) share upool
  // Overlay B: Ast (20480B) / wsmT (3328B) share astpool
  __shared__ __align__(16) char upool[NPIX * FS * 4];       // 6656B
  __shared__ __align__(16) uint32_t astpool[NTHREADS * NA]; // 20480B

  uint32_t* tile = reinterpret_cast<uint32_t*>(upool);     // [TH][TW][NPR]
  float*    feat = reinterpret_cast<float*>(upool);        // [NPIX][FS]
  uint32_t* Ast  = astpool;                                // [NTHREADS][NA]
  float*    wsmT = reinterpret_cast<float*>(astpool);      // [16][FS] (epilogue)

  const int tid = threadIdx.x;
  const int bx = blockIdx.x, by = blockIdx.y, bz = blockIdx.z;

  // haloed tile -> smem as half2; vectorized: float4 per 4 channels
  const int y0 = by * TY - 3, x0 = bx * TX - 3;
  for (int i = tid; i < TH * TW * 4; i += NTHREADS) {
    int q   = i & 3;       // channel quad
    int pos = i >> 2;      // 0..TH*TW-1
    int py = pos / TW, px = pos - py * TW;
    int gy = y0 + py, gx = x0 + px;
    uint2 vv; vv.x = 0u; vv.y = 0u;
    if ((unsigned)gy < (unsigned)Hn && (unsigned)gx < (unsigned)Wn) {
      const float4 f = *reinterpret_cast<const float4*>(
          &x[(((bz * Hn + gy) * Wn) + gx) * Cn + q * 4]);
      vv.x = h2u(__floats2half2_rn(f.x, f.y));
      vv.y = h2u(__floats2half2_rn(f.z, f.w));
    }
    *reinterpret_cast<uint2*>(&tile[pos * NPR + q * 2]) = vv;
  }
  __syncthreads();

  const int c2  = tid & (NPR - 1);   // channel pair
  const int pix = tid >> 3;          // 0..31
  __half2 m7, m3, m5;
  {
    const int pxx = pix & (TX - 1);
    const int pyy = pix >> 3;
    const uint32_t* baseu = &tile[(((pyy + 3) * TW) + (pxx + 3)) * NPR + c2];
    const uint32_t tb = s2u(baseu);
    const uint32_t ab = s2u(&Ast[tid * NA]);

    __half2 V[49];
    // inner 3x3 -> slots 0..8
#pragma unroll
    for (int dy = -1; dy <= 1; dy++)
#pragma unroll
      for (int dx = -1; dx <= 1; dx++)
        V[(dy + 1) * 3 + (dx + 1)] = u2h(baseu[(dy * TW + dx) * NPR]);
    // 5x5 ring -> slots 9..24
    {
      int k = 9;
#pragma unroll
      for (int dy = -2; dy <= 2; dy++)
#pragma unroll
        for (int dx = -2; dx <= 2; dx++)
          if (dy < -1 || dy > 1 || dx < -1 || dx > 1) { V[k] = u2h(baseu[(dy * TW + dx) * NPR]); k++; }
    }

    // k=3: ascending index 6 of sorted 9
    S9::run(V);
    m3 = V[Get<6, typename S9::type>::value];

    // k=5: ascending index 14 of sorted 25
    S16::run(V);
    M25::run(V);
    m5 = V[Get<14, A25>::value];

    // keep the three earliest-needed ranks in registers; stage the rest
    const __half2 A2 = V[Get<2, A25>::value];
    const __half2 A3 = V[Get<3, A25>::value];
    const __half2 A4 = V[Get<4, A25>::value];
    Stage<5>::run(V, ab);

    // 7x7 ring -> slots 25..48 (opaque LDS: cannot hoist above staging)
    {
      int k = 25;
#pragma unroll
      for (int dy = -3; dy <= 3; dy++)
#pragma unroll
        for (int dx = -3; dx <= 3; dx++)
          if (dy < -2 || dy > 2 || dx < -2 || dx > 2) { V[k] = u2h(lds_u(tb + (dy * TW + dx) * (NPR * 4))); k++; }
    }

    S24::run(V);

    // k=7: rank 26 of union: m7 = max(A[2], B[1], max_{i=3..24} min(A[i], B[26-i]))
    {
      __half2 accE = __hmax2(A2, V[Get<1, B24>::value]);            // A[2], B[1]
      __half2 accO = __hmin2(A3, V[Get<23, B24>::value]);           // i=3
      accE = __hmax2(accE, __hmin2(A4, V[Get<22, B24>::value]));    // i=4

      __half2 a[8];
      // group 1: A[5..12]
#pragma unroll
      for (int r = 0; r < 8; r++) a[r] = u2h(lds_u(ab + r * 4));
      accO = __hmax2(accO, SelA<5, 11, 5>::run(V, a));              // i=5,7,9,11
      accE = __hmax2(accE, SelA<6, 12, 5>::run(V, a));              // i=6,8,10,12
      // group 2: A[13..20]
#pragma unroll
      for (int r = 0; r < 8; r++) a[r] = u2h(lds_u(ab + (8 + r) * 4));
      accO = __hmax2(accO, SelA<13, 19, 13>::run(V, a));            // i=13,15,17,19
      accE = __hmax2(accE, SelA<14, 20, 13>::run(V, a));            // i=14,16,18,20
      // group 3: A[21..24]
#pragma unroll
      for (int r = 0; r < 4; r++) a[r] = u2h(lds_u(ab + (16 + r) * 4));
      accO = __hmax2(accO, SelA<21, 23, 21>::run(V, a));            // i=21,23
      accE = __hmax2(accE, SelA<22, 24, 21>::run(V, a));            // i=22,24
      m7 = __hmax2(accE, accO);
    }
  }

  // tile and Ast are dead; feat overlays tile, wsmT overlays Ast.
  __syncthreads();
  {
    float* fp = &feat[pix * FS];
    float2 f7 = __half22float2(m7);
    float2 f3 = __half22float2(m3);
    float2 f5 = __half22float2(m5);
    *reinterpret_cast<float2*>(&fp[     2 * c2]) = f7;
    *reinterpret_cast<float2*>(&fp[16 + 2 * c2]) = f3;
    *reinterpret_cast<float2*>(&fp[32 + 2 * c2]) = f5;
  }
  // transposed weights into the (dead) staging buffer: wsmT[o*FS+cc] = w[cc*16+o]
  for (int i = tid; i < 16 * 48; i += NTHREADS) {
    int o = i & 15, cc = i >> 4;
    wsmT[o * FS + cc] = w[cc * 16 + o];
  }
  __syncthreads();

  // fused 1x1 conv (fp32): thread computes output channel o for 2 pixels
  {
    const int o  = tid & 15;
    const int p0 = tid >> 4;                 // pixels p0 and p0+16
    const float4* wrow = reinterpret_cast<const float4*>(&wsmT[o * FS]);
    const float4* f0   = reinterpret_cast<const float4*>(&feat[p0 * FS]);
    const float4* f1   = reinterpret_cast<const float4*>(&feat[(p0 + 16) * FS]);
    float acc0 = 0.f, acc1 = 0.f;
#pragma unroll
    for (int q = 0; q < 12; q++) {
      const float4 wv = wrow[q];
      const float4 av = f0[q];
      const float4 bv = f1[q];
      acc0 = fmaf(av.x, wv.x, acc0); acc1 = fmaf(bv.x, wv.x, acc1);
      acc0 = fmaf(av.y, wv.y, acc0); acc1 = fmaf(bv.y, wv.y, acc1);
      acc0 = fmaf(av.z, wv.z, acc0); acc1 = fmaf(bv.z, wv.z, acc1);
      acc0 = fmaf(av.w, wv.w, acc0); acc1 = fmaf(bv.w, wv.w, acc1);
    }
    const int px0 = p0 & (TX - 1), py0 = p0 >> 3;
    const int px1 = (p0 + 16) & (TX - 1), py1 = (p0 + 16) >> 3;
    out[(((bz * Hn + by * TY + py0) * Wn) + bx * TX + px0) * Cn + o] = acc0;
    out[(((bz * Hn + by * TY + py1) * Wn) + bx * TX + px1) * Cn + o] = acc1;
  }
}

extern "C" void kernel_launch(void* const* d_in, const int* in_sizes, int n_in,
                              void* d_out, int out_size) {
  const float* x = (const float*)d_in[0];
  const float* w = (const float*)d_in[1];
  float* out = (float*)d_out;
  dim3 grid(Wn / TX, Hn / TY, Bn);
  amblock_kernel<<<grid, NTHREADS>>>(x, w, out);
}

// round 12
// speedup vs baseline: 1.1180x; 1.0007x over previous
#include <cuda_runtime.h>
#include <cuda_fp16.h>
#include <cstdint>

#define DEVINL static __device__ __forceinline__

// ===================== compile-time int-list machinery =====================
template<int... Is> struct IL { static constexpr int size = sizeof...(Is); };

template<int H, typename L> struct Prepend;
template<int H, int... Is> struct Prepend<H, IL<Is...>> { using type = IL<H, Is...>; };

template<typename A, typename B> struct Concat;
template<int... As, int... Bs> struct Concat<IL<As...>, IL<Bs...>> { using type = IL<As..., Bs...>; };

template<int I, typename L> struct Get;
template<int H, int... T> struct Get<0, IL<H, T...>> { static constexpr int value = H; };
template<int I, int H, int... T> struct Get<I, IL<H, T...>> { static constexpr int value = Get<I-1, IL<T...>>::value; };

template<int N, typename L> struct Take;
template<> struct Take<0, IL<>> { using type = IL<>; };
template<int H, int... T> struct Take<0, IL<H, T...>> { using type = IL<>; };
template<int N, int H, int... T> struct Take<N, IL<H, T...>> {
  using type = typename Prepend<H, typename Take<N-1, IL<T...>>::type>::type;
};

template<int N, typename L> struct Drop;
template<> struct Drop<0, IL<>> { using type = IL<>; };
template<int H, int... T> struct Drop<0, IL<H, T...>> { using type = IL<H, T...>; };
template<int N, int H, int... T> struct Drop<N, IL<H, T...>> { using type = typename Drop<N-1, IL<T...>>::type; };

template<typename L> struct EvenOdd;
template<> struct EvenOdd<IL<>> { using even = IL<>; using odd = IL<>; };
template<int A> struct EvenOdd<IL<A>> { using even = IL<A>; using odd = IL<>; };
template<int A, int Bv, int... R> struct EvenOdd<IL<A, Bv, R...>> {
  using even = typename Prepend<A,  typename EvenOdd<IL<R...>>::even>::type;
  using odd  = typename Prepend<Bv, typename EvenOdd<IL<R...>>::odd >::type;
};

template<typename E, typename O> struct Interleave;
template<typename E> struct Interleave<E, IL<>> { using type = E; };
template<int E0, int... Es, int O0, int... Os>
struct Interleave<IL<E0, Es...>, IL<O0, Os...>> {
  using type = typename Concat<IL<E0, O0>, typename Interleave<IL<Es...>, IL<Os...>>::type>::type;
};

// ===================== packed f16x2 compare-exchange =====================
DEVINL void cas_(__half2& x, __half2& y) {
  __half2 lo = __hmin2(x, y);
  __half2 hi = __hmax2(x, y);
  x = lo; y = hi;
}

// cleanup step of odd-even merge: cas(O[i], E[i+1])
template<typename E, typename O> struct Cleanup {
  DEVINL void run(__half2*) {}
};
template<int E0, int E1, int... Es, int O0, int... Os>
struct Cleanup<IL<E0, E1, Es...>, IL<O0, Os...>> {
  DEVINL void run(__half2* v) {
    cas_(v[O0], v[E1]);
    Cleanup<IL<E1, Es...>, IL<Os...>>::run(v);
  }
};

// ===================== generalized Batcher odd-even merge =====================
template<typename A, typename B, int M = A::size, int N = B::size>
struct Merge {
  using ME = Merge<typename EvenOdd<A>::even, typename EvenOdd<B>::even>;
  using MO = Merge<typename EvenOdd<A>::odd,  typename EvenOdd<B>::odd >;
  using E = typename ME::type;
  using O = typename MO::type;
  using type = typename Interleave<E, O>::type;
  DEVINL void run(__half2* v) { ME::run(v); MO::run(v); Cleanup<E, O>::run(v); }
};
template<typename A, typename B, int N> struct Merge<A, B, 0, N> { using type = B; DEVINL void run(__half2*) {} };
template<typename A, typename B, int M> struct Merge<A, B, M, 0> { using type = A; DEVINL void run(__half2*) {} };
template<typename A, typename B>        struct Merge<A, B, 0, 0> { using type = IL<>; DEVINL void run(__half2*) {} };
template<typename A, typename B> struct Merge<A, B, 1, 1> {
  static constexpr int a0 = Get<0, A>::value;
  static constexpr int b0 = Get<0, B>::value;
  using type = IL<a0, b0>;
  DEVINL void run(__half2* v) { cas_(v[a0], v[b0]); }
};

// odd-even merge sort
template<typename L, int N = L::size>
struct Sort {
  static constexpr int Half = N / 2;
  using SA = Sort<typename Take<Half, L>::type>;
  using SB = Sort<typename Drop<Half, L>::type>;
  using MG = Merge<typename SA::type, typename SB::type>;
  using type = typename MG::type;
  DEVINL void run(__half2* v) { SA::run(v); SB::run(v); MG::run(v); }
};
template<typename L> struct Sort<L, 0> { using type = IL<>; DEVINL void run(__half2*) {} };
template<typename L> struct Sort<L, 1> { using type = L;    DEVINL void run(__half2*) {} };

template<int S, int N> struct Range {
  using type = typename Prepend<S, typename Range<S+1, N-1>::type>::type;
};
template<int S> struct Range<S, 0> { using type = IL<>; };

// ===================== opaque smem ld/st + bit casts =====================
DEVINL uint32_t s2u(const void* p) { return (uint32_t)__cvta_generic_to_shared(p); }
DEVINL void sts_u(uint32_t a, uint32_t v) {
  asm volatile("st.shared.b32 [%0], %1;" :: "r"(a), "r"(v) : "memory");
}
DEVINL uint32_t lds_u(uint32_t a) {
  uint32_t v;
  asm volatile("ld.shared.b32 %0, [%1];" : "=r"(v) : "r"(a) : "memory");
  return v;
}
DEVINL uint32_t h2u(__half2 h) { return *reinterpret_cast<uint32_t*>(&h); }
DEVINL __half2 u2h(uint32_t u) { return *reinterpret_cast<__half2*>(&u); }

// ===================== problem constants =====================
constexpr int Bn = 4, Hn = 256, Wn = 256, Cn = 16;
constexpr int TX = 8, TY = 4;              // output pixels per block: 32
constexpr int TW = TX + 6, TH = TY + 6;    // 14 x 10 haloed tile
constexpr int NPIX = TX * TY;              // 32
constexpr int NPR  = Cn / 2;               // 8 channel-pairs
constexpr int NTHREADS = NPIX * NPR;       // 256
constexpr int NA = 21;                     // staging stride (odd -> conflict-free); words 0..19 used
constexpr int FS = 52;                     // feat / wsmT row stride (16B-aligned)

// single smem pool, two phases:
//   phase 1: tile [0, 4480) + Ast [4480, 25984)
//   phase 2: feat [0, 6656) + wsmT [6656, 9984)   (overlays dead phase-1 data)
constexpr int SM_TILE = 0;
constexpr int SM_AST  = TH * TW * NPR * 4;          // 4480
constexpr int SM_FEAT = 0;
constexpr int SM_WT   = NPIX * FS * 4;              // 6656
constexpr int SM_TOTAL = SM_AST + NTHREADS * NA * 4; // 25984

// Slot layout of V: 0..8 inner 3x3, 9..24 ring of 5x5, 25..48 ring of 7x7
using L9  = Range<0, 9>::type;
using L16 = Range<9, 16>::type;
using L24 = Range<25, 24>::type;
using S9  = Sort<L9>;
using S16 = Sort<L16>;
using S24 = Sort<L24>;
using M25 = Merge<typename S9::type, typename S16::type>;
using A25 = typename M25::type;
using B24 = typename S24::type;

// Stage sorted25 ranks R..24 (R starts at 5) to smem
template<int R> struct Stage {
  DEVINL void run(const __half2* v, uint32_t ab) {
    sts_u(ab + (R - 5) * 4, h2u(v[Get<R, A25>::value]));
    Stage<R + 1>::run(v, ab);
  }
};
template<> struct Stage<25> { DEVINL void run(const __half2*, uint32_t) {} };

// Selection fold over terms t_i = min(a[i-OFS], B24[26-i]) for i = I, I+2, ...
template<int I, int IEnd, int OFS> struct SelA {
  DEVINL __half2 run(const __half2* v, const __half2* a) {
    __half2 t = __hmin2(a[I - OFS], v[Get<26 - I, B24>::value]);
    return __hmax2(t, SelA<I + 2, IEnd, OFS>::run(v, a));
  }
};
template<int IEnd, int OFS> struct SelA<IEnd, IEnd, OFS> {
  DEVINL __half2 run(const __half2* v, const __half2* a) {
    return __hmin2(a[IEnd - OFS], v[Get<26 - IEnd, B24>::value]);
  }
};

__global__ void __launch_bounds__(NTHREADS, 8)
amblock_kernel(const float* __restrict__ x, const float* __restrict__ w,
               float* __restrict__ out) {
  __shared__ __align__(16) char pool[SM_TOTAL];     // 25984B

  uint32_t* tile = reinterpret_cast<uint32_t*>(pool + SM_TILE); // [TH][TW][NPR]
  uint32_t* Ast  = reinterpret_cast<uint32_t*>(pool + SM_AST);  // [NTHREADS][NA]
  float*    feat = reinterpret_cast<float*>(pool + SM_FEAT);    // [NPIX][FS]  (phase 2)
  float*    wsmT = reinterpret_cast<float*>(pool + SM_WT);      // [16][FS]    (phase 2)

  const int tid = threadIdx.x;
  const int bx = blockIdx.x, by = blockIdx.y, bz = blockIdx.z;

  // haloed tile -> smem as half2; vectorized: float4 per 4 channels
  const int y0 = by * TY - 3, x0 = bx * TX - 3;
  for (int i = tid; i < TH * TW * 4; i += NTHREADS) {
    int q   = i & 3;       // channel quad
    int pos = i >> 2;      // 0..TH*TW-1
    int py = pos / TW, px = pos - py * TW;
    int gy = y0 + py, gx = x0 + px;
    uint2 vv; vv.x = 0u; vv.y = 0u;
    if ((unsigned)gy < (unsigned)Hn && (unsigned)gx < (unsigned)Wn) {
      const float4 f = *reinterpret_cast<const float4*>(
          &x[(((bz * Hn + gy) * Wn) + gx) * Cn + q * 4]);
      vv.x = h2u(__floats2half2_rn(f.x, f.y));
      vv.y = h2u(__floats2half2_rn(f.z, f.w));
    }
    *reinterpret_cast<uint2*>(&tile[pos * NPR + q * 2]) = vv;
  }
  __syncthreads();

  const int c2  = tid & (NPR - 1);   // channel pair
  const int pix = tid >> 3;          // 0..31
  __half2 m7, m3, m5;
  {
    const int pxx = pix & (TX - 1);
    const int pyy = pix >> 3;
    const uint32_t* baseu = &tile[(((pyy + 3) * TW) + (pxx + 3)) * NPR + c2];
    const uint32_t tb = s2u(baseu);
    const uint32_t ab = s2u(&Ast[tid * NA]);

    __half2 V[49];
    // inner 3x3 -> slots 0..8
#pragma unroll
    for (int dy = -1; dy <= 1; dy++)
#pragma unroll
      for (int dx = -1; dx <= 1; dx++)
        V[(dy + 1) * 3 + (dx + 1)] = u2h(baseu[(dy * TW + dx) * NPR]);
    // 5x5 ring -> slots 9..24
    {
      int k = 9;
#pragma unroll
      for (int dy = -2; dy <= 2; dy++)
#pragma unroll
        for (int dx = -2; dx <= 2; dx++)
          if (dy < -1 || dy > 1 || dx < -1 || dx > 1) { V[k] = u2h(baseu[(dy * TW + dx) * NPR]); k++; }
    }

    // k=3: ascending index 6 of sorted 9
    S9::run(V);
    m3 = V[Get<6, typename S9::type>::value];

    // k=5: ascending index 14 of sorted 25
    S16::run(V);
    M25::run(V);
    m5 = V[Get<14, A25>::value];

    // keep the three earliest-needed ranks in registers; stage the rest
    const __half2 A2 = V[Get<2, A25>::value];
    const __half2 A3 = V[Get<3, A25>::value];
    const __half2 A4 = V[Get<4, A25>::value];
    Stage<5>::run(V, ab);

    // 7x7 ring -> slots 25..48 (opaque LDS: cannot hoist above staging)
    {
      int k = 25;
#pragma unroll
      for (int dy = -3; dy <= 3; dy++)
#pragma unroll
        for (int dx = -3; dx <= 3; dx++)
          if (dy < -2 || dy > 2 || dx < -2 || dx > 2) { V[k] = u2h(lds_u(tb + (dy * TW + dx) * (NPR * 4))); k++; }
    }

    S24::run(V);

    // k=7: rank 26 of union: m7 = max(A[2], B[1], max_{i=3..24} min(A[i], B[26-i]))
    {
      __half2 accE = __hmax2(A2, V[Get<1, B24>::value]);            // A[2], B[1]
      __half2 accO = __hmin2(A3, V[Get<23, B24>::value]);           // i=3
      accE = __hmax2(accE, __hmin2(A4, V[Get<22, B24>::value]));    // i=4

      __half2 a[8];
      // group 1: A[5..12]
#pragma unroll
      for (int r = 0; r < 8; r++) a[r] = u2h(lds_u(ab + r * 4));
      accO = __hmax2(accO, SelA<5, 11, 5>::run(V, a));              // i=5,7,9,11
      accE = __hmax2(accE, SelA<6, 12, 5>::run(V, a));              // i=6,8,10,12
      // group 2: A[13..20]
#pragma unroll
      for (int r = 0; r < 8; r++) a[r] = u2h(lds_u(ab + (8 + r) * 4));
      accO = __hmax2(accO, SelA<13, 19, 13>::run(V, a));            // i=13,15,17,19
      accE = __hmax2(accE, SelA<14, 20, 13>::run(V, a));            // i=14,16,18,20
      // group 3: A[21..24]
#pragma unroll
      for (int r = 0; r < 4; r++) a[r] = u2h(lds_u(ab + (16 + r) * 4));
      accO = __hmax2(accO, SelA<21, 23, 21>::run(V, a));            // i=21,23
      accE = __hmax2(accE, SelA<22, 24, 21>::run(V, a));            // i=22,24
      m7 = __hmax2(accE, accO);
    }
  }

  // phase 1 data (tile, Ast) is dead; phase 2 overlays it. Barrier first.
  __syncthreads();
  {
    float* fp = &feat[pix * FS];
    float2 f7 = __half22float2(m7);
    float2 f3 = __half22float2(m3);
    float2 f5 = __half22float2(m5);
    *reinterpret_cast<float2*>(&fp[     2 * c2]) = f7;
    *reinterpret_cast<float2*>(&fp[16 + 2 * c2]) = f3;
    *reinterpret_cast<float2*>(&fp[32 + 2 * c2]) = f5;
  }
  // transposed weights: wsmT[o*FS+cc] = w[cc*16+o]
  for (int i = tid; i < 16 * 48; i += NTHREADS) {
    int o = i & 15, cc = i >> 4;
    wsmT[o * FS + cc] = w[cc * 16 + o];
  }
  __syncthreads();

  // fused 1x1 conv (fp32): thread computes output channel o for 2 pixels
  {
    const int o  = tid & 15;
    const int p0 = tid >> 4;                 // pixels p0 and p0+16
    const float4* wrow = reinterpret_cast<const float4*>(&wsmT[o * FS]);
    const float4* f0   = reinterpret_cast<const float4*>(&feat[p0 * FS]);
    const float4* f1   = reinterpret_cast<const float4*>(&feat[(p0 + 16) * FS]);
    float acc0 = 0.f, acc1 = 0.f;
#pragma unroll
    for (int q = 0; q < 12; q++) {
      const float4 wv = wrow[q];
      const float4 av = f0[q];
      const float4 bv = f1[q];
      acc0 = fmaf(av.x, wv.x, acc0); acc1 = fmaf(bv.x, wv.x, acc1);
      acc0 = fmaf(av.y, wv.y, acc0); acc1 = fmaf(bv.y, wv.y, acc1);
      acc0 = fmaf(av.z, wv.z, acc0); acc1 = fmaf(bv.z, wv.z, acc1);
      acc0 = fmaf(av.w, wv.w, acc0); acc1 = fmaf(bv.w, wv.w, acc1);
    }
    const int px0 = p0 & (TX - 1), py0 = p0 >> 3;
    const int px1 = (p0 + 16) & (TX - 1), py1 = (p0 + 16) >> 3;
    out[(((bz * Hn + by * TY + py0) * Wn) + bx * TX + px0) * Cn + o] = acc0;
    out[(((bz * Hn + by * TY + py1) * Wn) + bx * TX + px1) * Cn + o] = acc1;
  }
}

extern "C" void kernel_launch(void* const* d_in, const int* in_sizes, int n_in,
                              void* d_out, int out_size) {
  const float* x = (const float*)d_in[0];
  const float* w = (const float*)d_in[1];
  float* out = (float*)d_out;
  dim3 grid(Wn / TX, Hn / TY, Bn);
  amblock_kernel<<<grid, NTHREADS>>>(x, w, out);
}

// round 13
// speedup vs baseline: 1.1188x; 1.0007x over previous
#include <cuda_runtime.h>
#include <cuda_fp16.h>
#include <cstdint>

#define DEVINL static __device__ __forceinline__

// ===================== compile-time int-list machinery =====================
template<int... Is> struct IL { static constexpr int size = sizeof...(Is); };

template<int H, typename L> struct Prepend;
template<int H, int... Is> struct Prepend<H, IL<Is...>> { using type = IL<H, Is...>; };

template<typename A, typename B> struct Concat;
template<int... As, int... Bs> struct Concat<IL<As...>, IL<Bs...>> { using type = IL<As..., Bs...>; };

template<int I, typename L> struct Get;
template<int H, int... T> struct Get<0, IL<H, T...>> { static constexpr int value = H; };
template<int I, int H, int... T> struct Get<I, IL<H, T...>> { static constexpr int value = Get<I-1, IL<T...>>::value; };

template<int N, typename L> struct Take;
template<> struct Take<0, IL<>> { using type = IL<>; };
template<int H, int... T> struct Take<0, IL<H, T...>> { using type = IL<>; };
template<int N, int H, int... T> struct Take<N, IL<H, T...>> {
  using type = typename Prepend<H, typename Take<N-1, IL<T...>>::type>::type;
};

template<int N, typename L> struct Drop;
template<> struct Drop<0, IL<>> { using type = IL<>; };
template<int H, int... T> struct Drop<0, IL<H, T...>> { using type = IL<H, T...>; };
template<int N, int H, int... T> struct Drop<N, IL<H, T...>> { using type = typename Drop<N-1, IL<T...>>::type; };

template<typename L> struct EvenOdd;
template<> struct EvenOdd<IL<>> { using even = IL<>; using odd = IL<>; };
template<int A> struct EvenOdd<IL<A>> { using even = IL<A>; using odd = IL<>; };
template<int A, int Bv, int... R> struct EvenOdd<IL<A, Bv, R...>> {
  using even = typename Prepend<A,  typename EvenOdd<IL<R...>>::even>::type;
  using odd  = typename Prepend<Bv, typename EvenOdd<IL<R...>>::odd >::type;
};

template<typename E, typename O> struct Interleave;
template<typename E> struct Interleave<E, IL<>> { using type = E; };
template<int E0, int... Es, int O0, int... Os>
struct Interleave<IL<E0, Es...>, IL<O0, Os...>> {
  using type = typename Concat<IL<E0, O0>, typename Interleave<IL<Es...>, IL<Os...>>::type>::type;
};

// ===================== packed f16x2 compare-exchange =====================
DEVINL void cas_(__half2& x, __half2& y) {
  __half2 lo = __hmin2(x, y);
  __half2 hi = __hmax2(x, y);
  x = lo; y = hi;
}

// cleanup step of odd-even merge: cas(O[i], E[i+1])
template<typename E, typename O> struct Cleanup {
  DEVINL void run(__half2*) {}
};
template<int E0, int E1, int... Es, int O0, int... Os>
struct Cleanup<IL<E0, E1, Es...>, IL<O0, Os...>> {
  DEVINL void run(__half2* v) {
    cas_(v[O0], v[E1]);
    Cleanup<IL<E1, Es...>, IL<Os...>>::run(v);
  }
};

// ===================== generalized Batcher odd-even merge =====================
template<typename A, typename B, int M = A::size, int N = B::size>
struct Merge {
  using ME = Merge<typename EvenOdd<A>::even, typename EvenOdd<B>::even>;
  using MO = Merge<typename EvenOdd<A>::odd,  typename EvenOdd<B>::odd >;
  using E = typename ME::type;
  using O = typename MO::type;
  using type = typename Interleave<E, O>::type;
  DEVINL void run(__half2* v) { ME::run(v); MO::run(v); Cleanup<E, O>::run(v); }
};
template<typename A, typename B, int N> struct Merge<A, B, 0, N> { using type = B; DEVINL void run(__half2*) {} };
template<typename A, typename B, int M> struct Merge<A, B, M, 0> { using type = A; DEVINL void run(__half2*) {} };
template<typename A, typename B>        struct Merge<A, B, 0, 0> { using type = IL<>; DEVINL void run(__half2*) {} };
template<typename A, typename B> struct Merge<A, B, 1, 1> {
  static constexpr int a0 = Get<0, A>::value;
  static constexpr int b0 = Get<0, B>::value;
  using type = IL<a0, b0>;
  DEVINL void run(__half2* v) { cas_(v[a0], v[b0]); }
};

// odd-even merge sort
template<typename L, int N = L::size>
struct Sort {
  static constexpr int Half = N / 2;
  using SA = Sort<typename Take<Half, L>::type>;
  using SB = Sort<typename Drop<Half, L>::type>;
  using MG = Merge<typename SA::type, typename SB::type>;
  using type = typename MG::type;
  DEVINL void run(__half2* v) { SA::run(v); SB::run(v); MG::run(v); }
};
template<typename L> struct Sort<L, 0> { using type = IL<>; DEVINL void run(__half2*) {} };
template<typename L> struct Sort<L, 1> { using type = L;    DEVINL void run(__half2*) {} };

template<int S, int N> struct Range {
  using type = typename Prepend<S, typename Range<S+1, N-1>::type>::type;
};
template<int S> struct Range<S, 0> { using type = IL<>; };

// ===================== opaque smem ld/st + bit casts =====================
DEVINL uint32_t s2u(const void* p) { return (uint32_t)__cvta_generic_to_shared(p); }
DEVINL void sts_u(uint32_t a, uint32_t v) {
  asm volatile("st.shared.b32 [%0], %1;" :: "r"(a), "r"(v) : "memory");
}
DEVINL uint32_t lds_u(uint32_t a) {
  uint32_t v;
  asm volatile("ld.shared.b32 %0, [%1];" : "=r"(v) : "r"(a) : "memory");
  return v;
}
DEVINL uint32_t h2u(__half2 h) { return *reinterpret_cast<uint32_t*>(&h); }
DEVINL __half2 u2h(uint32_t u) { return *reinterpret_cast<__half2*>(&u); }

// ===================== problem constants =====================
constexpr int Bn = 4, Hn = 256, Wn = 256, Cn = 16;
constexpr int TX = 8, TY = 4;              // output pixels per block: 32
constexpr int TW = TX + 6, TH = TY + 6;    // 14 x 10 haloed tile
constexpr int NPIX = TX * TY;              // 32
constexpr int NPR  = Cn / 2;               // 8 channel-pairs
constexpr int NTHREADS = NPIX * NPR;       // 256
constexpr int NA = 21;                     // staging stride (odd -> conflict-free); words 0..19 used
constexpr int FS = 52;                     // feat / wsmT row stride (16B-aligned)

// single smem pool, two phases:
//   phase 1: tile [0, 4480) + Ast [4480, 25984)
//   phase 2: feat [0, 6656) + wsmT [6656, 9984)   (overlays dead phase-1 data)
constexpr int SM_TILE = 0;
constexpr int SM_AST  = TH * TW * NPR * 4;          // 4480
constexpr int SM_FEAT = 0;
constexpr int SM_WT   = NPIX * FS * 4;              // 6656
constexpr int SM_TOTAL = SM_AST + NTHREADS * NA * 4; // 25984

// Slot layout of V: 0..8 inner 3x3, 9..24 ring of 5x5, 25..48 ring of 7x7
using L9  = Range<0, 9>::type;
using L16 = Range<9, 16>::type;
using L24 = Range<25, 24>::type;
using S9  = Sort<L9>;
using S16 = Sort<L16>;
using S24 = Sort<L24>;
using M25 = Merge<typename S9::type, typename S16::type>;
using A25 = typename M25::type;
using B24 = typename S24::type;

// Stage sorted25 ranks R..24 (R starts at 5) to smem
template<int R> struct Stage {
  DEVINL void run(const __half2* v, uint32_t ab) {
    sts_u(ab + (R - 5) * 4, h2u(v[Get<R, A25>::value]));
    Stage<R + 1>::run(v, ab);
  }
};
template<> struct Stage<25> { DEVINL void run(const __half2*, uint32_t) {} };

// Selection fold over terms t_i = min(a[i-OFS], B24[26-i]) for i = I, I+2, ...
template<int I, int IEnd, int OFS> struct SelA {
  DEVINL __half2 run(const __half2* v, const __half2* a) {
    __half2 t = __hmin2(a[I - OFS], v[Get<26 - I, B24>::value]);
    return __hmax2(t, SelA<I + 2, IEnd, OFS>::run(v, a));
  }
};
template<int IEnd, int OFS> struct SelA<IEnd, IEnd, OFS> {
  DEVINL __half2 run(const __half2* v, const __half2* a) {
    return __hmin2(a[IEnd - OFS], v[Get<26 - IEnd, B24>::value]);
  }
};

__global__ void __launch_bounds__(NTHREADS, 8)
amblock_kernel(const float* __restrict__ x, const float* __restrict__ w,
               float* __restrict__ out) {
  __shared__ __align__(16) char pool[SM_TOTAL];     // 25984B

  uint32_t* tile = reinterpret_cast<uint32_t*>(pool + SM_TILE); // [TH][TW][NPR]
  uint32_t* Ast  = reinterpret_cast<uint32_t*>(pool + SM_AST);  // [NTHREADS][NA]
  float*    feat = reinterpret_cast<float*>(pool + SM_FEAT);    // [NPIX][FS]  (phase 2)
  float*    wsmT = reinterpret_cast<float*>(pool + SM_WT);      // [16][FS]    (phase 2)

  const int tid = threadIdx.x;
  const int bx = blockIdx.x, by = blockIdx.y, bz = blockIdx.z;

  // haloed tile -> smem as half2; vectorized: float4 per 4 channels
  const int y0 = by * TY - 3, x0 = bx * TX - 3;
  for (int i = tid; i < TH * TW * 4; i += NTHREADS) {
    int q   = i & 3;       // channel quad
    int pos = i >> 2;      // 0..TH*TW-1
    int py = pos / TW, px = pos - py * TW;
    int gy = y0 + py, gx = x0 + px;
    uint2 vv; vv.x = 0u; vv.y = 0u;
    if ((unsigned)gy < (unsigned)Hn && (unsigned)gx < (unsigned)Wn) {
      const float4 f = *reinterpret_cast<const float4*>(
          &x[(((bz * Hn + gy) * Wn) + gx) * Cn + q * 4]);
      vv.x = h2u(__floats2half2_rn(f.x, f.y));
      vv.y = h2u(__floats2half2_rn(f.z, f.w));
    }
    *reinterpret_cast<uint2*>(&tile[pos * NPR + q * 2]) = vv;
  }
  __syncthreads();

  const int c2  = tid & (NPR - 1);   // channel pair
  const int pix = tid >> 3;          // 0..31
  __half2 m7, m3, m5;
  {
    const int pxx = pix & (TX - 1);
    const int pyy = pix >> 3;
    const uint32_t* baseu = &tile[(((pyy + 3) * TW) + (pxx + 3)) * NPR + c2];
    const uint32_t tb = s2u(baseu);
    const uint32_t ab = s2u(&Ast[tid * NA]);

    __half2 V[49];
    // inner 3x3 -> slots 0..8
#pragma unroll
    for (int dy = -1; dy <= 1; dy++)
#pragma unroll
      for (int dx = -1; dx <= 1; dx++)
        V[(dy + 1) * 3 + (dx + 1)] = u2h(baseu[(dy * TW + dx) * NPR]);
    // 5x5 ring -> slots 9..24
    {
      int k = 9;
#pragma unroll
      for (int dy = -2; dy <= 2; dy++)
#pragma unroll
        for (int dx = -2; dx <= 2; dx++)
          if (dy < -1 || dy > 1 || dx < -1 || dx > 1) { V[k] = u2h(baseu[(dy * TW + dx) * NPR]); k++; }
    }

    // k=3: ascending index 6 of sorted 9
    S9::run(V);
    m3 = V[Get<6, typename S9::type>::value];

    // k=5: ascending index 14 of sorted 25
    S16::run(V);
    M25::run(V);
    m5 = V[Get<14, A25>::value];

    // keep the three earliest-needed ranks in registers; stage the rest
    const __half2 A2 = V[Get<2, A25>::value];
    const __half2 A3 = V[Get<3, A25>::value];
    const __half2 A4 = V[Get<4, A25>::value];
    Stage<5>::run(V, ab);

    // 7x7 ring -> slots 25..48 (opaque LDS: cannot hoist above staging)
    {
      int k = 25;
#pragma unroll
      for (int dy = -3; dy <= 3; dy++)
#pragma unroll
        for (int dx = -3; dx <= 3; dx++)
          if (dy < -2 || dy > 2 || dx < -2 || dx > 2) { V[k] = u2h(lds_u(tb + (dy * TW + dx) * (NPR * 4))); k++; }
    }

    S24::run(V);

    // k=7: rank 26 of union: m7 = max(A[2], B[1], max_{i=3..24} min(A[i], B[26-i]))
    {
      __half2 accE = __hmax2(A2, V[Get<1, B24>::value]);            // A[2], B[1]
      __half2 accO = __hmin2(A3, V[Get<23, B24>::value]);           // i=3
      accE = __hmax2(accE, __hmin2(A4, V[Get<22, B24>::value]));    // i=4

      __half2 a[8];
      // group 1: A[5..12]
#pragma unroll
      for (int r = 0; r < 8; r++) a[r] = u2h(lds_u(ab + r * 4));
      accO = __hmax2(accO, SelA<5, 11, 5>::run(V, a));              // i=5,7,9,11
      accE = __hmax2(accE, SelA<6, 12, 5>::run(V, a));              // i=6,8,10,12
      // group 2: A[13..20]
#pragma unroll
      for (int r = 0; r < 8; r++) a[r] = u2h(lds_u(ab + (8 + r) * 4));
      accO = __hmax2(accO, SelA<13, 19, 13>::run(V, a));            // i=13,15,17,19
      accE = __hmax2(accE, SelA<14, 20, 13>::run(V, a));            // i=14,16,18,20
      // group 3: A[21..24]
#pragma unroll
      for (int r = 0; r < 4; r++) a[r] = u2h(lds_u(ab + (16 + r) * 4));
      accO = __hmax2(accO, SelA<21, 23, 21>::run(V, a));            // i=21,23
      accE = __hmax2(accE, SelA<22, 24, 21>::run(V, a));            // i=22,24
      m7 = __hmax2(accE, accO);
    }
  }

  // phase 1 data (tile, Ast) is dead; phase 2 overlays it. Barrier first.
  __syncthreads();
  {
    float* fp = &feat[pix * FS];
    float2 f7 = __half22float2(m7);
    float2 f3 = __half22float2(m3);
    float2 f5 = __half22float2(m5);
    *reinterpret_cast<float2*>(&fp[     2 * c2]) = f7;
    *reinterpret_cast<float2*>(&fp[16 + 2 * c2]) = f3;
    *reinterpret_cast<float2*>(&fp[32 + 2 * c2]) = f5;
  }
  // transposed weights: wsmT[o*FS+cc] = w[cc*16+o]
  for (int i = tid; i < 16 * 48; i += NTHREADS) {
    int o = i & 15, cc = i >> 4;
    wsmT[o * FS + cc] = w[cc * 16 + o];
  }
  __syncthreads();

  // fused 1x1 conv (fp32): thread computes output channel o for 2 pixels
  {
    const int o  = tid & 15;
    const int p0 = tid >> 4;                 // pixels p0 and p0+16
    const float4* wrow = reinterpret_cast<const float4*>(&wsmT[o * FS]);
    const float4* f0   = reinterpret_cast<const float4*>(&feat[p0 * FS]);
    const float4* f1   = reinterpret_cast<const float4*>(&feat[(p0 + 16) * FS]);
    float acc0 = 0.f, acc1 = 0.f;
#pragma unroll
    for (int q = 0; q < 12; q++) {
      const float4 wv = wrow[q];
      const float4 av = f0[q];
      const float4 bv = f1[q];
      acc0 = fmaf(av.x, wv.x, acc0); acc1 = fmaf(bv.x, wv.x, acc1);
      acc0 = fmaf(av.y, wv.y, acc0); acc1 = fmaf(bv.y, wv.y, acc1);
      acc0 = fmaf(av.z, wv.z, acc0); acc1 = fmaf(bv.z, wv.z, acc1);
      acc0 = fmaf(av.w, wv.w, acc0); acc1 = fmaf(bv.w, wv.w, acc1);
    }
    const int px0 = p0 & (TX - 1), py0 = p0 >> 3;
    const int px1 = (p0 + 16) & (TX - 1), py1 = (p0 + 16) >> 3;
    out[(((bz * Hn + by * TY + py0) * Wn) + bx * TX + px0) * Cn + o] = acc0;
    out[(((bz * Hn + by * TY + py1) * Wn) + bx * TX + px1) * Cn + o] = acc1;
  }
}

extern "C" void kernel_launch(void* const* d_in, const int* in_sizes, int n_in,
                              void* d_out, int out_size) {
  const float* x = (const float*)d_in[0];
  const float* w = (const float*)d_in[1];
  float* out = (float*)d_out;
  dim3 grid(Wn / TX, Hn / TY, Bn);
  amblock_kernel<<<grid, NTHREADS>>>(x, w, out);
}

// round 15
// speedup vs baseline: 1.1405x; 1.0195x over previous
#include <cuda_runtime.h>
#include <cuda_fp16.h>
#include <cstdint>

#define DEVINL static __device__ __forceinline__

// ===================== compile-time int-list machinery =====================
template<int... Is> struct IL { static constexpr int size = sizeof...(Is); };

template<int H, typename L> struct Prepend;
template<int H, int... Is> struct Prepend<H, IL<Is...>> { using type = IL<H, Is...>; };

template<typename A, typename B> struct Concat;
template<int... As, int... Bs> struct Concat<IL<As...>, IL<Bs...>> { using type = IL<As..., Bs...>; };

template<int I, typename L> struct Get;
template<int H, int... T> struct Get<0, IL<H, T...>> { static constexpr int value = H; };
template<int I, int H, int... T> struct Get<I, IL<H, T...>> { static constexpr int value = Get<I-1, IL<T...>>::value; };

template<int N, typename L> struct Take;
template<> struct Take<0, IL<>> { using type = IL<>; };
template<int H, int... T> struct Take<0, IL<H, T...>> { using type = IL<>; };
template<int N, int H, int... T> struct Take<N, IL<H, T...>> {
  using type = typename Prepend<H, typename Take<N-1, IL<T...>>::type>::type;
};

template<int N, typename L> struct Drop;
template<> struct Drop<0, IL<>> { using type = IL<>; };
template<int H, int... T> struct Drop<0, IL<H, T...>> { using type = IL<H, T...>; };
template<int N, int H, int... T> struct Drop<N, IL<H, T...>> { using type = typename Drop<N-1, IL<T...>>::type; };

template<typename L> struct EvenOdd;
template<> struct EvenOdd<IL<>> { using even = IL<>; using odd = IL<>; };
template<int A> struct EvenOdd<IL<A>> { using even = IL<A>; using odd = IL<>; };
template<int A, int Bv, int... R> struct EvenOdd<IL<A, Bv, R...>> {
  using even = typename Prepend<A,  typename EvenOdd<IL<R...>>::even>::type;
  using odd  = typename Prepend<Bv, typename EvenOdd<IL<R...>>::odd >::type;
};

template<typename E, typename O> struct Interleave;
template<typename E> struct Interleave<E, IL<>> { using type = E; };
template<int E0, int... Es, int O0, int... Os>
struct Interleave<IL<E0, Es...>, IL<O0, Os...>> {
  using type = typename Concat<IL<E0, O0>, typename Interleave<IL<Es...>, IL<Os...>>::type>::type;
};

// ===================== packed f16x2 compare-exchange =====================
DEVINL void cas_(__half2& x, __half2& y) {
  __half2 lo = __hmin2(x, y);
  __half2 hi = __hmax2(x, y);
  x = lo; y = hi;
}

// cleanup step of odd-even merge: cas(O[i], E[i+1])
template<typename E, typename O> struct Cleanup {
  DEVINL void run(__half2*) {}
};
template<int E0, int E1, int... Es, int O0, int... Os>
struct Cleanup<IL<E0, E1, Es...>, IL<O0, Os...>> {
  DEVINL void run(__half2* v) {
    cas_(v[O0], v[E1]);
    Cleanup<IL<E1, Es...>, IL<Os...>>::run(v);
  }
};

// ===================== generalized Batcher odd-even merge =====================
template<typename A, typename B, int M = A::size, int N = B::size>
struct Merge {
  using ME = Merge<typename EvenOdd<A>::even, typename EvenOdd<B>::even>;
  using MO = Merge<typename EvenOdd<A>::odd,  typename EvenOdd<B>::odd >;
  using E = typename ME::type;
  using O = typename MO::type;
  using type = typename Interleave<E, O>::type;
  DEVINL void run(__half2* v) { ME::run(v); MO::run(v); Cleanup<E, O>::run(v); }
};
template<typename A, typename B, int N> struct Merge<A, B, 0, N> { using type = B; DEVINL void run(__half2*) {} };
template<typename A, typename B, int M> struct Merge<A, B, M, 0> { using type = A; DEVINL void run(__half2*) {} };
template<typename A, typename B>        struct Merge<A, B, 0, 0> { using type = IL<>; DEVINL void run(__half2*) {} };
template<typename A, typename B> struct Merge<A, B, 1, 1> {
  static constexpr int a0 = Get<0, A>::value;
  static constexpr int b0 = Get<0, B>::value;
  using type = IL<a0, b0>;
  DEVINL void run(__half2* v) { cas_(v[a0], v[b0]); }
};

// odd-even merge sort
template<typename L, int N = L::size>
struct Sort {
  static constexpr int Half = N / 2;
  using SA = Sort<typename Take<Half, L>::type>;
  using SB = Sort<typename Drop<Half, L>::type>;
  using MG = Merge<typename SA::type, typename SB::type>;
  using type = typename MG::type;
  DEVINL void run(__half2* v) { SA::run(v); SB::run(v); MG::run(v); }
};
template<typename L> struct Sort<L, 0> { using type = IL<>; DEVINL void run(__half2*) {} };
template<typename L> struct Sort<L, 1> { using type = L;    DEVINL void run(__half2*) {} };

template<int S, int N> struct Range {
  using type = typename Prepend<S, typename Range<S+1, N-1>::type>::type;
};
template<int S> struct Range<S, 0> { using type = IL<>; };

// ===================== opaque smem ld/st + bit casts =====================
DEVINL uint32_t s2u(const void* p) { return (uint32_t)__cvta_generic_to_shared(p); }
DEVINL void sts_u64(uint32_t a, uint32_t x, uint32_t y) {
  asm volatile("st.shared.v2.u32 [%0], {%1, %2};" :: "r"(a), "r"(x), "r"(y) : "memory");
}
DEVINL void lds_u64(uint32_t a, uint32_t& x, uint32_t& y) {
  asm volatile("ld.shared.v2.u32 {%0, %1}, [%2];" : "=r"(x), "=r"(y) : "r"(a) : "memory");
}
DEVINL uint32_t h2u(__half2 h) { return *reinterpret_cast<uint32_t*>(&h); }
DEVINL __half2 u2h(uint32_t u) { return *reinterpret_cast<__half2*>(&u); }

// ===================== problem constants =====================
constexpr int Bn = 4, Hn = 256, Wn = 256, Cn = 16;
constexpr int TX = 8, TY = 4;               // 32 output pixels per block
constexpr int TW = TX + 6, TH = TY + 6;     // 14 x 10 haloed tile
constexpr int NPIX = TX * TY;               // 32
constexpr int NTHREADS = NPIX * 4;          // 128: thread = (pixel, channel-quad)
constexpr int NSLOT = 25;                   // staging slots/thread (A[2..24], m3, m5), 8B each
constexpr int FS = 52;                      // feat / wsmT row stride (16B-aligned)

// single smem pool, two phases:
//   phase 1: tile [0, 4480) + Ast [4480, 30080)
//   phase 2: feat [0, 6656) + wsmT [6656, 9984)
constexpr int SM_TILE = 0;
constexpr int SM_AST  = TH * TW * 8 * 4;              // 4480
constexpr int SM_WT   = NPIX * FS * 4;                // 6656
constexpr int SM_TOTAL = SM_AST + NTHREADS * NSLOT * 8; // 30080

// Slot layout of V: 0..8 inner 3x3, 9..24 ring of 5x5, 25..48 ring of 7x7
using L9  = Range<0, 9>::type;
using L16 = Range<9, 16>::type;
using L24 = Range<25, 24>::type;
using S9  = Sort<L9>;
using S16 = Sort<L16>;
using S24 = Sort<L24>;
using M25 = Merge<typename S9::type, typename S16::type>;
using A25 = typename M25::type;
using B24 = typename S24::type;

// Stage sorted25 ranks R..24 for BOTH networks (one STS.64 per rank)
template<int R> struct Stage2 {
  DEVINL void run(const __half2* v0, const __half2* v1, uint32_t ab) {
    sts_u64(ab + (R - 2) * 8, h2u(v0[Get<R, A25>::value]), h2u(v1[Get<R, A25>::value]));
    Stage2<R + 1>::run(v0, v1, ab);
  }
};
template<> struct Stage2<25> { DEVINL void run(const __half2*, const __half2*, uint32_t) {} };

// Selection fold: terms t_i = min(a[i-OFS], B24[26-i]) for i = I, I+2, ..., IEnd
template<int I, int IEnd, int OFS> struct SelA {
  DEVINL __half2 run(const __half2* v, const __half2* a) {
    __half2 t = __hmin2(a[I - OFS], v[Get<26 - I, B24>::value]);
    return __hmax2(t, SelA<I + 2, IEnd, OFS>::run(v, a));
  }
};
template<int IEnd, int OFS> struct SelA<IEnd, IEnd, OFS> {
  DEVINL __half2 run(const __half2* v, const __half2* a) {
    return __hmin2(a[IEnd - OFS], v[Get<26 - IEnd, B24>::value]);
  }
};

// rank-26 selection for one network, reloading A-ranks in groups of 4 (uint2
// loads shared with the sibling network are done by the caller into a0/a1).
#define SEL_GROUP(net, G0)                                                     \
  accO##net = __hmax2(accO##net, (SelA<G0 + 1, G0 + 3, G0>::run(V##net, a##net))); \
  accE##net = __hmax2(accE##net, (SelA<G0,     G0 + 2, G0>::run(V##net, a##net)));

__global__ void __launch_bounds__(NTHREADS, 7)
amblock_kernel(const float* __restrict__ x, const float* __restrict__ w,
               float* __restrict__ out) {
  __shared__ __align__(16) char pool[SM_TOTAL];

  uint32_t* tile = reinterpret_cast<uint32_t*>(pool + SM_TILE); // [TH*TW][8]
  float*    feat = reinterpret_cast<float*>(pool);              // [NPIX][FS] (phase 2)
  float*    wsmT = reinterpret_cast<float*>(pool + SM_WT);      // [16][FS]   (phase 2)

  const int tid = threadIdx.x;
  const int bx = blockIdx.x, by = blockIdx.y, bz = blockIdx.z;

  // haloed tile -> smem as half2; float4 global loads (4 channels/op)
  const int y0 = by * TY - 3, x0 = bx * TX - 3;
  for (int i = tid; i < TH * TW * 4; i += NTHREADS) {
    int q   = i & 3;
    int pos = i >> 2;
    int py = pos / TW, px = pos - py * TW;
    int gy = y0 + py, gx = x0 + px;
    uint2 vv; vv.x = 0u; vv.y = 0u;
    if ((unsigned)gy < (unsigned)Hn && (unsigned)gx < (unsigned)Wn) {
      const float4 f = *reinterpret_cast<const float4*>(
          &x[(((bz * Hn + gy) * Wn) + gx) * Cn + q * 4]);
      vv.x = h2u(__floats2half2_rn(f.x, f.y));
      vv.y = h2u(__floats2half2_rn(f.z, f.w));
    }
    *reinterpret_cast<uint2*>(&tile[pos * 8 + q * 2]) = vv;
  }
  __syncthreads();

  const int q   = tid & 3;           // channel quad: nets cover pairs 2q, 2q+1
  const int pix = tid >> 2;          // 0..31
  {
    const int pxx = pix & (TX - 1);
    const int pyy = pix >> 3;
    const uint32_t tb = s2u(&tile[(((pyy + 3) * TW) + (pxx + 3)) * 8 + q * 2]);
    const uint32_t ab = s2u(pool + SM_AST) + tid * (NSLOT * 8);

    __half2 V0[49], V1[49];
    // inner 3x3 + 5x5 ring, both nets via one LDS.64 per position
    {
      uint32_t vx, vy;
#pragma unroll
      for (int dy = -1; dy <= 1; dy++)
#pragma unroll
        for (int dx = -1; dx <= 1; dx++) {
          lds_u64(tb + (dy * TW + dx) * 32, vx, vy);
          int k = (dy + 1) * 3 + (dx + 1);
          V0[k] = u2h(vx); V1[k] = u2h(vy);
        }
      int k = 9;
#pragma unroll
      for (int dy = -2; dy <= 2; dy++)
#pragma unroll
        for (int dx = -2; dx <= 2; dx++)
          if (dy < -1 || dy > 1 || dx < -1 || dx > 1) {
            lds_u64(tb + (dy * TW + dx) * 32, vx, vy);
            V0[k] = u2h(vx); V1[k] = u2h(vy); k++;
          }
    }

    // k=3 / k=5 for both nets
    S9::run(V0);  S9::run(V1);
    const __half2 m3_0 = V0[Get<6, typename S9::type>::value];
    const __half2 m3_1 = V1[Get<6, typename S9::type>::value];
    S16::run(V0); S16::run(V1);
    M25::run(V0); M25::run(V1);

    // stage A[2..24] (both nets, uint2 per rank) + m3/m5 in slots 23/24
    sts_u64(ab + 23 * 8, h2u(m3_0), h2u(m3_1));
    sts_u64(ab + 24 * 8, h2u(V0[Get<14, A25>::value]), h2u(V1[Get<14, A25>::value]));
    Stage2<2>::run(V0, V1, ab);

    // 7x7 ring -> slots 25..48, both nets (opaque -> cannot hoist above staging)
    {
      uint32_t vx, vy;
      int k = 25;
#pragma unroll
      for (int dy = -3; dy <= 3; dy++)
#pragma unroll
        for (int dx = -3; dx <= 3; dx++)
          if (dy < -2 || dy > 2 || dx < -2 || dx > 2) {
            lds_u64(tb + (dy * TW + dx) * 32, vx, vy);
            V0[k] = u2h(vx); V1[k] = u2h(vy); k++;
          }
    }

    S24::run(V0); S24::run(V1);   // independent networks -> ILP=2

    // rank 26 of union for both nets; A-ranks reloaded once (uint2) per group
    __half2 a0[4], a1[4];
    __half2 accE0, accO0, accE1, accO1;
    {
      uint32_t vx, vy;
      // group ranks 2..5: specials A[2], B[1]; terms i=3,4,5
#pragma unroll
      for (int r = 0; r < 4; r++) { lds_u64(ab + r * 8, vx, vy); a0[r] = u2h(vx); a1[r] = u2h(vy); }
      accE0 = __hmax2(a0[0], V0[Get<1, B24>::value]);
      accE1 = __hmax2(a1[0], V1[Get<1, B24>::value]);
      accO0 = __hmin2(a0[1], V0[Get<23, B24>::value]);
      accO1 = __hmin2(a1[1], V1[Get<23, B24>::value]);
      accE0 = __hmax2(accE0, __hmin2(a0[2], V0[Get<22, B24>::value]));
      accE1 = __hmax2(accE1, __hmin2(a1[2], V1[Get<22, B24>::value]));
      accO0 = __hmax2(accO0, __hmin2(a0[3], V0[Get<21, B24>::value]));
      accO1 = __hmax2(accO1, __hmin2(a1[3], V1[Get<21, B24>::value]));
      // groups of 4 ranks: 6..9, 10..13, 14..17, 18..21
#pragma unroll
      for (int r = 0; r < 4; r++) { lds_u64(ab + (4 + r) * 8, vx, vy); a0[r] = u2h(vx); a1[r] = u2h(vy); }
      SEL_GROUP(0, 6)  SEL_GROUP(1, 6)
#pragma unroll
      for (int r = 0; r < 4; r++) { lds_u64(ab + (8 + r) * 8, vx, vy); a0[r] = u2h(vx); a1[r] = u2h(vy); }
      SEL_GROUP(0, 10) SEL_GROUP(1, 10)
#pragma unroll
      for (int r = 0; r < 4; r++) { lds_u64(ab + (12 + r) * 8, vx, vy); a0[r] = u2h(vx); a1[r] = u2h(vy); }
      SEL_GROUP(0, 14) SEL_GROUP(1, 14)
#pragma unroll
      for (int r = 0; r < 4; r++) { lds_u64(ab + (16 + r) * 8, vx, vy); a0[r] = u2h(vx); a1[r] = u2h(vy); }
      SEL_GROUP(0, 18) SEL_GROUP(1, 18)
      // group ranks 22..24: terms i=22,23,24
#pragma unroll
      for (int r = 0; r < 3; r++) { lds_u64(ab + (20 + r) * 8, vx, vy); a0[r] = u2h(vx); a1[r] = u2h(vy); }
      accE0 = __hmax2(accE0, SelA<22, 24, 22>::run(V0, a0));
      accE1 = __hmax2(accE1, SelA<22, 24, 22>::run(V1, a1));
      accO0 = __hmax2(accO0, SelA<23, 23, 22>::run(V0, a0));
      accO1 = __hmax2(accO1, SelA<23, 23, 22>::run(V1, a1));
    }
    const __half2 m7_0 = __hmax2(accE0, accO0);
    const __half2 m7_1 = __hmax2(accE1, accO1);

    // pull staged m3/m5 back (before the phase-2 overlay clobbers Ast)
    uint32_t m3x, m3y, m5x, m5y;
    lds_u64(ab + 23 * 8, m3x, m3y);
    lds_u64(ab + 24 * 8, m5x, m5y);

    // phase 1 data dead; phase 2 overlays it
    __syncthreads();
    {
      float* fp = &feat[pix * FS];
      const float2 a7 = __half22float2(m7_0), b7 = __half22float2(m7_1);
      const float2 a3 = __half22float2(u2h(m3x)), b3 = __half22float2(u2h(m3y));
      const float2 a5 = __half22float2(u2h(m5x)), b5 = __half22float2(u2h(m5y));
      *reinterpret_cast<float4*>(&fp[     4 * q]) = make_float4(a7.x, a7.y, b7.x, b7.y);
      *reinterpret_cast<float4*>(&fp[16 + 4 * q]) = make_float4(a3.x, a3.y, b3.x, b3.y);
      *reinterpret_cast<float4*>(&fp[32 + 4 * q]) = make_float4(a5.x, a5.y, b5.x, b5.y);
    }
  }
  // transposed weights: wsmT[o*FS+cc] = w[cc*16+o]
  for (int i = tid; i < 16 * 48; i += NTHREADS) {
    int o = i & 15, cc = i >> 4;
    wsmT[o * FS + cc] = w[cc * 16 + o];
  }
  __syncthreads();

  // fused 1x1 conv (fp32): thread computes output channel o for 4 pixels
  {
    const int o = tid & 15;
    const int p = tid >> 4;                  // pixels p, p+8, p+16, p+24
    const float4* wrow = reinterpret_cast<const float4*>(&wsmT[o * FS]);
    const float4* f0 = reinterpret_cast<const float4*>(&feat[p * FS]);
    const float4* f1 = reinterpret_cast<const float4*>(&feat[(p + 8) * FS]);
    const float4* f2 = reinterpret_cast<const float4*>(&feat[(p + 16) * FS]);
    const float4* f3 = reinterpret_cast<const float4*>(&feat[(p + 24) * FS]);
    float acc0 = 0.f, acc1 = 0.f, acc2 = 0.f, acc3 = 0.f;
#pragma unroll
    for (int qq = 0; qq < 12; qq++) {
      const float4 wv = wrow[qq];
      const float4 av = f0[qq], bv = f1[qq], cv = f2[qq], dv = f3[qq];
      acc0 = fmaf(av.x, wv.x, acc0); acc1 = fmaf(bv.x, wv.x, acc1);
      acc2 = fmaf(cv.x, wv.x, acc2); acc3 = fmaf(dv.x, wv.x, acc3);
      acc0 = fmaf(av.y, wv.y, acc0); acc1 = fmaf(bv.y, wv.y, acc1);
      acc2 = fmaf(cv.y, wv.y, acc2); acc3 = fmaf(dv.y, wv.y, acc3);
      acc0 = fmaf(av.z, wv.z, acc0); acc1 = fmaf(bv.z, wv.z, acc1);
      acc2 = fmaf(cv.z, wv.z, acc2); acc3 = fmaf(dv.z, wv.z, acc3);
      acc0 = fmaf(av.w, wv.w, acc0); acc1 = fmaf(bv.w, wv.w, acc1);
      acc2 = fmaf(cv.w, wv.w, acc2); acc3 = fmaf(dv.w, wv.w, acc3);
    }
    // pixel p+8j has pyy=j, pxx=p
    const int gx = bx * TX + p;
#pragma unroll
    for (int j = 0; j < 4; j++) {
      const float acc = (j == 0) ? acc0 : (j == 1) ? acc1 : (j == 2) ? acc2 : acc3;
      out[(((bz * Hn + by * TY + j) * Wn) + gx) * Cn + o] = acc;
    }
  }
}

extern "C" void kernel_launch(void* const* d_in, const int* in_sizes, int n_in,
                              void* d_out, int out_size) {
  const float* x = (const float*)d_in[0];
  const float* w = (const float*)d_in[1];
  float* out = (float*)d_out;
  dim3 grid(Wn / TX, Hn / TY, Bn);
  amblock_kernel<<<grid, NTHREADS>>>(x, w, out);
}